// round 7
// baseline (speedup 1.0000x reference)
#include <cuda_runtime.h>
#include <cuda_bf16.h>
#include <cstdint>

#define BB 8
#define LXX 2048
#define LYY 2048
#define DD 256

// ---------------- global scratch (no cudaMalloc allowed) ----------------
__device__ __nv_bfloat16 g_xp_h[BB * LXX * DD];
__device__ __nv_bfloat16 g_xp_l[BB * LXX * DD];
__device__ __nv_bfloat16 g_yp_h[BB * LYY * DD];
__device__ __nv_bfloat16 g_yp_l[BB * LYY * DD];
__device__ __nv_bfloat16 g_yv_h[BB * LYY * DD];   // raw y, bf16 hi
__device__ __nv_bfloat16 g_yv_l[BB * LYY * DD];   // raw y, bf16 lo

// ---------------- helpers (portable PTX only: sm_80-era) ----------------
__device__ __forceinline__ uint32_t smem_u32(const void* p) {
    uint32_t a;
    asm("{ .reg .u64 t; cvta.to.shared.u64 t, %1; cvt.u32.u64 %0, t; }" : "=r"(a) : "l"(p));
    return a;
}
__device__ __forceinline__ void cpa16(uint32_t s, const void* g) {
    asm volatile("cp.async.cg.shared.global [%0], [%1], 16;" :: "r"(s), "l"(g));
}
__device__ __forceinline__ void cpa4(uint32_t s, const void* g) {
    asm volatile("cp.async.ca.shared.global [%0], [%1], 4;" :: "r"(s), "l"(g));
}
#define CP_COMMIT() asm volatile("cp.async.commit_group;" ::: "memory")
#define CP_WAIT0()  asm volatile("cp.async.wait_group 0;" ::: "memory")
#define CP_WAIT1()  asm volatile("cp.async.wait_group 1;" ::: "memory")

__device__ __forceinline__ void ldsm4(uint32_t r[4], uint32_t a) {
    asm volatile("ldmatrix.sync.aligned.m8n8.x4.shared.b16 {%0,%1,%2,%3}, [%4];"
                 : "=r"(r[0]), "=r"(r[1]), "=r"(r[2]), "=r"(r[3]) : "r"(a));
}
__device__ __forceinline__ void ldsm4t(uint32_t r[4], uint32_t a) {
    asm volatile("ldmatrix.sync.aligned.m8n8.x4.trans.shared.b16 {%0,%1,%2,%3}, [%4];"
                 : "=r"(r[0]), "=r"(r[1]), "=r"(r[2]), "=r"(r[3]) : "r"(a));
}
__device__ __forceinline__ void mma16816(float c[4], const uint32_t a[4],
                                         uint32_t b0, uint32_t b1) {
    asm volatile(
        "mma.sync.aligned.m16n8k16.row.col.f32.bf16.bf16.f32 "
        "{%0,%1,%2,%3}, {%4,%5,%6,%7}, {%8,%9}, {%0,%1,%2,%3};"
        : "+f"(c[0]), "+f"(c[1]), "+f"(c[2]), "+f"(c[3])
        : "r"(a[0]), "r"(a[1]), "r"(a[2]), "r"(a[3]), "r"(b0), "r"(b1));
}
__device__ __forceinline__ uint32_t cvt2bf(float lo, float hi) {
    uint32_t r;
    asm("cvt.rn.bf16x2.f32 %0, %1, %2;" : "=r"(r) : "f"(hi), "f"(lo));
    return r;
}
__device__ __forceinline__ float exp2p(float t) {
    t = fmaxf(t, -126.0f);
    float n = rintf(t);
    float f = t - n;
    float p = fmaf(1.5403530e-4f, f, 1.3333558e-3f);
    p = fmaf(p, f, 9.6181290e-3f);
    p = fmaf(p, f, 5.5504109e-2f);
    p = fmaf(p, f, 2.4022651e-1f);
    p = fmaf(p, f, 6.9314718e-1f);
    p = fmaf(p, f, 1.0f);
    return p * __int_as_float(((int)n + 127) << 23);
}
#define L2E 1.4426950408889634f

// ---------------------------------------------------------------------------
// Projection (fp32 SIMT) -> bf16 hi/lo splits. C = relu(A @ W^T + b)
// ---------------------------------------------------------------------------
__global__ __launch_bounds__(256, 1)
void proj_kernel(const float* __restrict__ A,
                 const float* __restrict__ W,
                 const float* __restrict__ bias,
                 int which)
{
    __shared__ float As[16][132];
    __shared__ float Bs[16][132];

    const int tid = threadIdx.x;
    const int tx = tid & 15;
    const int ty = tid >> 4;
    const int row0 = blockIdx.y * 128;
    const int col0 = blockIdx.x * 128;

    __nv_bfloat16* __restrict__ Ch = which ? g_yp_h : g_xp_h;
    __nv_bfloat16* __restrict__ Cl = which ? g_yp_l : g_xp_l;

    float acc[8][8];
#pragma unroll
    for (int i = 0; i < 8; i++)
#pragma unroll
        for (int j = 0; j < 8; j++) acc[i][j] = 0.0f;

    for (int k0 = 0; k0 < DD; k0 += 16) {
#pragma unroll
        for (int e = 0; e < 8; e++) {
            int elem = tid + e * 256;
            int kk = elem & 15;
            int r  = elem >> 4;
            As[kk][r] = A[(size_t)(row0 + r) * DD + k0 + kk];
            Bs[kk][r] = W[(size_t)(col0 + r) * DD + k0 + kk];
        }
        __syncthreads();
#pragma unroll
        for (int kk = 0; kk < 16; kk++) {
            float4 a0 = *(const float4*)&As[kk][ty * 8];
            float4 a1 = *(const float4*)&As[kk][ty * 8 + 4];
            float4 b0 = *(const float4*)&Bs[kk][tx * 8];
            float4 b1 = *(const float4*)&Bs[kk][tx * 8 + 4];
            float a[8] = {a0.x, a0.y, a0.z, a0.w, a1.x, a1.y, a1.z, a1.w};
            float bq[8] = {b0.x, b0.y, b0.z, b0.w, b1.x, b1.y, b1.z, b1.w};
#pragma unroll
            for (int i = 0; i < 8; i++)
#pragma unroll
                for (int j = 0; j < 8; j++)
                    acc[i][j] = fmaf(a[i], bq[j], acc[i][j]);
        }
        __syncthreads();
    }

    float bv[8];
#pragma unroll
    for (int j = 0; j < 8; j++) bv[j] = bias[col0 + tx * 8 + j];

#pragma unroll
    for (int i = 0; i < 8; i++) {
        int row = row0 + ty * 8 + i;
        __nv_bfloat16 hb[8], lb[8];
#pragma unroll
        for (int j = 0; j < 8; j++) {
            float v = fmaxf(acc[i][j] + bv[j], 0.0f);
            __nv_bfloat16 h = __float2bfloat16_rn(v);
            hb[j] = h;
            lb[j] = __float2bfloat16_rn(v - __bfloat162float(h));
        }
        size_t o = (size_t)row * DD + col0 + tx * 8;
        *(uint4*)&Ch[o] = *(uint4*)hb;
        *(uint4*)&Cl[o] = *(uint4*)lb;
    }
}

// ---------------------------------------------------------------------------
// Elementwise y -> bf16 hi/lo (natural [b][tok][d] layout)
// ---------------------------------------------------------------------------
__global__ __launch_bounds__(256)
void split_y(const float* __restrict__ y)
{
    size_t i = ((size_t)blockIdx.x * 256 + threadIdx.x) * 4;
    float4 v = *(const float4*)(y + i);
    float vv[4] = {v.x, v.y, v.z, v.w};
    __nv_bfloat16 h[4], l[4];
#pragma unroll
    for (int k = 0; k < 4; k++) {
        h[k] = __float2bfloat16_rn(vv[k]);
        l[k] = __float2bfloat16_rn(vv[k] - __bfloat162float(h[k]));
    }
    *(uint2*)&g_yv_h[i] = *(uint2*)h;
    *(uint2*)&g_yv_l[i] = *(uint2*)l;
}

// ---------------------------------------------------------------------------
// Fused mma.sync attention, 512 threads.
// 16 warps = 8 row-groups x 2 halves. Warp: 16 rows x (16 S-cols, 128 O-cols).
// P exchanged through smem (bf16 h/l). Softmax max/sum combined via smem.
// Lifetime-split cp.async pipelining preserved (Yp overlaps PV, yV overlaps S).
// ---------------------------------------------------------------------------
#define SXSTR 528
#define SXH 0
#define SXL 67584
#define SBH 135168
#define SBL 152064
#define SVH 168960
#define SVL 185856
#define SPH 202752          // P hi: 128 rows x 80B
#define SPL 212992          // P lo
#define SMK 223232          // 32 ints
#define SRM 223360          // partial max: 128 x 2 floats
#define SRS 224384          // partial sum: 128 x 2 floats
#define SMTOT 225408
#define NT (LYY / 32)

__global__ __launch_bounds__(512, 1)
void attn_mma_kernel(const int* __restrict__ mask, float* __restrict__ out)
{
    extern __shared__ char smc[];
    const uint32_t sa = smem_u32(smc);
    const int tid  = threadIdx.x;
    const int w    = tid >> 5;
    const int lane = tid & 31;
    const int lr   = lane >> 2;
    const int tig  = lane & 3;
    const int wg   = w >> 1;          // row-group 0..7
    const int wh   = w & 1;           // S-col / O-col half
    const int rw   = wg * 16;
    const int b    = blockIdx.y;
    const int x0   = blockIdx.x * 128;

    const int* mB = mask + (size_t)b * LYY;
    const size_t gyB = (size_t)(b * LYY) * DD;
    const int pr = tid >> 4;                 // 0..31 (tile row)
    const int pc2 = (tid & 15) * 2;          // chunk pair

    auto issueYp = [&](int t) {
        size_t gro = gyB + (size_t)(t * 32 + pr) * DD;
        uint32_t o = sa + (uint32_t)(pr * SXSTR);
#pragma unroll
        for (int q = 0; q < 2; q++) {
            int c = pc2 + q;
            cpa16(o + SBH + c * 16, g_yp_h + gro + c * 8);
            cpa16(o + SBL + c * 16, g_yp_l + gro + c * 8);
        }
        if (tid < 32) cpa4(sa + SMK + tid * 4, mB + t * 32 + tid);
    };
    auto issueYv = [&](int t) {
        size_t gro = gyB + (size_t)(t * 32 + pr) * DD;
        uint32_t o = sa + (uint32_t)(pr * SXSTR);
#pragma unroll
        for (int q = 0; q < 2; q++) {
            int c = pc2 + q;
            cpa16(o + SVH + c * 16, g_yv_h + gro + c * 8);
            cpa16(o + SVL + c * 16, g_yv_l + gro + c * 8);
        }
    };

    // ---- prologue: X tile (group 0), Yp(0) (group 1), yV(0) (group 2) ----
    {
        int r = tid >> 2;
        int qb = (tid & 3) * 8;
        const __nv_bfloat16* srch = g_xp_h + (size_t)(b * LXX + x0 + r) * DD;
        const __nv_bfloat16* srcl = g_xp_l + (size_t)(b * LXX + x0 + r) * DD;
        uint32_t dh = sa + SXH + r * SXSTR;
        uint32_t dl = sa + SXL + r * SXSTR;
#pragma unroll
        for (int i = 0; i < 8; i++) {
            int c = qb + i;
            cpa16(dh + c * 16, srch + c * 8);
            cpa16(dl + c * 16, srcl + c * 8);
        }
    }
    CP_COMMIT();
    issueYp(0);
    CP_COMMIT();
    issueYv(0);
    CP_COMMIT();

    const int* smk = (const int*)(smc + SMK);
    float* sRMf = (float*)(smc + SRM);
    float* sRSf = (float*)(smc + SRS);

    float O[16][4];
#pragma unroll
    for (int i = 0; i < 16; i++) { O[i][0] = O[i][1] = O[i][2] = O[i][3] = 0.f; }
    float m0 = -1e30f, m1 = -1e30f, l0 = 0.f, l1 = 0.f;

    // ldmatrix addresses
    const uint32_t aA  = sa + SXH + (rw + (lane & 7) + ((lane >> 3) & 1) * 8) * SXSTR
                       + (lane >> 4) * 16;
    const uint32_t aAl = aA + (uint32_t)(SXL - SXH);
    const uint32_t aB  = sa + SBH + (wh * 16 + (lane & 7) + ((lane < 16) ? 0 : 8)) * SXSTR
                       + ((lane >> 3) & 1) * 16;
    const uint32_t aBl = aB + (uint32_t)(SBL - SBH);
    const uint32_t aV  = sa + SVH + ((lane & 7) + ((lane >> 3) & 1) * 8) * SXSTR
                       + wh * 256 + ((lane < 16) ? 0 : 16);
    const uint32_t aVl = aV + (uint32_t)(SVL - SVH);
    const uint32_t sPa = sa + SPH + (rw + (lane & 7) + ((lane >> 3) & 1) * 8) * 80
                       + (lane >> 4) * 16;
    const uint32_t sPaL = sPa + (uint32_t)(SPL - SPH);

    const int r0 = rw + lr, r1 = rw + lr + 8;

#pragma unroll 1
    for (int t = 0; t < NT; t++) {
        // wait: X + Yp(t) arrived (yV(t) may still be pending)
        CP_WAIT1();
        __syncthreads();

        // ---- S = Xp @ Yp^T (hh + hl + lh), 16 rows x 16 cols (this half) ----
        float sf[2][4];
#pragma unroll
        for (int nt = 0; nt < 2; nt++)
#pragma unroll
            for (int i = 0; i < 4; i++) sf[nt][i] = 0.f;

#pragma unroll 4
        for (int kk = 0; kk < 16; kk++) {
            uint32_t ah[4], al[4], bh[4], bl[4];
            ldsm4(ah, aA  + kk * 32);
            ldsm4(al, aAl + kk * 32);
            ldsm4(bh, aB  + kk * 32);
            ldsm4(bl, aBl + kk * 32);
            mma16816(sf[0], ah, bh[0], bh[1]);
            mma16816(sf[0], ah, bl[0], bl[1]);
            mma16816(sf[0], al, bh[0], bh[1]);
            mma16816(sf[1], ah, bh[2], bh[3]);
            mma16816(sf[1], ah, bl[2], bl[3]);
            mma16816(sf[1], al, bh[2], bh[3]);
        }

        // ---- mask + partial row max ----
        float mx0 = -1e30f, mx1 = -1e30f;
#pragma unroll
        for (int nt = 0; nt < 2; nt++) {
            int j = wh * 16 + nt * 8 + 2 * tig;
            if (smk[j])     { sf[nt][0] = -1e30f; sf[nt][2] = -1e30f; }
            if (smk[j + 1]) { sf[nt][1] = -1e30f; sf[nt][3] = -1e30f; }
            mx0 = fmaxf(mx0, fmaxf(sf[nt][0], sf[nt][1]));
            mx1 = fmaxf(mx1, fmaxf(sf[nt][2], sf[nt][3]));
        }
        mx0 = fmaxf(mx0, __shfl_xor_sync(0xffffffffu, mx0, 1));
        mx0 = fmaxf(mx0, __shfl_xor_sync(0xffffffffu, mx0, 2));
        mx1 = fmaxf(mx1, __shfl_xor_sync(0xffffffffu, mx1, 1));
        mx1 = fmaxf(mx1, __shfl_xor_sync(0xffffffffu, mx1, 2));
        if (tig == 0) { sRMf[r0 * 2 + wh] = mx0; sRMf[r1 * 2 + wh] = mx1; }
        __syncthreads();    // (A) max partials visible; Yp/mask now dead

        // ---- overlap: issue Yp(t+1) during softmax + PV ----
        if (t < NT - 1) issueYp(t + 1);
        CP_COMMIT();

        float cm0 = fmaxf(sRMf[r0 * 2], sRMf[r0 * 2 + 1]);
        float cm1 = fmaxf(sRMf[r1 * 2], sRMf[r1 * 2 + 1]);
        float mn0 = fmaxf(m0, cm0), mn1 = fmaxf(m1, cm1);
        float sc0 = exp2p((m0 - mn0) * L2E);
        float sc1 = exp2p((m1 - mn1) * L2E);
        m0 = mn0; m1 = mn1;

        uint32_t ph[4], pl[4];
        float rs0 = 0.f, rs1 = 0.f;
#pragma unroll
        for (int nt = 0; nt < 2; nt++) {
            float p00 = exp2p((sf[nt][0] - mn0) * L2E);
            float p01 = exp2p((sf[nt][1] - mn0) * L2E);
            float p10 = exp2p((sf[nt][2] - mn1) * L2E);
            float p11 = exp2p((sf[nt][3] - mn1) * L2E);
            rs0 += p00 + p01;
            rs1 += p10 + p11;
            uint32_t h0 = cvt2bf(p00, p01);
            uint32_t h1 = cvt2bf(p10, p11);
            ph[nt * 2]     = h0;
            ph[nt * 2 + 1] = h1;
            float q00 = p00 - __uint_as_float(h0 << 16);
            float q01 = p01 - __uint_as_float(h0 & 0xffff0000u);
            float q10 = p10 - __uint_as_float(h1 << 16);
            float q11 = p11 - __uint_as_float(h1 & 0xffff0000u);
            pl[nt * 2]     = cvt2bf(q00, q01);
            pl[nt * 2 + 1] = cvt2bf(q10, q11);
        }
        rs0 += __shfl_xor_sync(0xffffffffu, rs0, 1);
        rs0 += __shfl_xor_sync(0xffffffffu, rs0, 2);
        rs1 += __shfl_xor_sync(0xffffffffu, rs1, 1);
        rs1 += __shfl_xor_sync(0xffffffffu, rs1, 2);

        // store P (h/l) to smem + partial sums
        {
            uint32_t cofs = (uint32_t)(wh * 32 + tig * 4);
#pragma unroll
            for (int nt = 0; nt < 2; nt++) {
                *(uint32_t*)(smc + SPH + r0 * 80 + cofs + nt * 16) = ph[nt * 2];
                *(uint32_t*)(smc + SPH + r1 * 80 + cofs + nt * 16) = ph[nt * 2 + 1];
                *(uint32_t*)(smc + SPL + r0 * 80 + cofs + nt * 16) = pl[nt * 2];
                *(uint32_t*)(smc + SPL + r1 * 80 + cofs + nt * 16) = pl[nt * 2 + 1];
            }
        }
        if (tig == 0) { sRSf[r0 * 2 + wh] = rs0; sRSf[r1 * 2 + wh] = rs1; }
        __syncthreads();    // (B) P + sum partials visible

        l0 = l0 * sc0 + (sRSf[r0 * 2] + sRSf[r0 * 2 + 1]);
        l1 = l1 * sc1 + (sRSf[r1 * 2] + sRSf[r1 * 2 + 1]);

        // O rescale while loads fly
#pragma unroll
        for (int od = 0; od < 16; od++) {
            O[od][0] *= sc0; O[od][1] *= sc0;
            O[od][2] *= sc1; O[od][3] *= sc1;
        }

        // wait for yV(t); last iter drain all
        if (t < NT - 1) { CP_WAIT1(); } else { CP_WAIT0(); }
        __syncthreads();    // (C)

        // ---- O += P @ y  (Ph.Vh + Ph.Vl + Pl.Vh), d-half per warp ----
#pragma unroll
        for (int kk = 0; kk < 2; kk++) {
            uint32_t pAh[4], pAl[4];
            ldsm4(pAh, sPa  + kk * 32);
            ldsm4(pAl, sPaL + kk * 32);
            uint32_t vb  = aV  + kk * 16 * SXSTR;
            uint32_t vbl = aVl + kk * 16 * SXSTR;
#pragma unroll
            for (int dg = 0; dg < 8; dg++) {
                uint32_t vh[4], vl[4];
                ldsm4t(vh, vb  + dg * 32);
                ldsm4t(vl, vbl + dg * 32);
                mma16816(O[2 * dg],     pAh, vh[0], vh[1]);
                mma16816(O[2 * dg],     pAh, vl[0], vl[1]);
                mma16816(O[2 * dg],     pAl, vh[0], vh[1]);
                mma16816(O[2 * dg + 1], pAh, vh[2], vh[3]);
                mma16816(O[2 * dg + 1], pAh, vl[2], vl[3]);
                mma16816(O[2 * dg + 1], pAl, vh[2], vh[3]);
            }
        }
        __syncthreads();    // (D) yV + P reads done

        if (t < NT - 1) issueYv(t + 1);
        CP_COMMIT();
    }

    // ---- epilogue: normalize + store (warp's d-half) ----
    float inv0 = 1.0f / l0, inv1 = 1.0f / l1;
    float* o0 = out + (size_t)(b * LXX + x0 + r0) * DD + wh * 128;
    float* o1 = out + (size_t)(b * LXX + x0 + r1) * DD + wh * 128;
#pragma unroll
    for (int od = 0; od < 16; od++) {
        int c = od * 8 + tig * 2;
        *(float2*)(o0 + c) = make_float2(O[od][0] * inv0, O[od][1] * inv0);
        *(float2*)(o1 + c) = make_float2(O[od][2] * inv1, O[od][3] * inv1);
    }
}

// ---------------------------------------------------------------------------
extern "C" void kernel_launch(void* const* d_in, const int* in_sizes, int n_in,
                              void* d_out, int out_size)
{
    const float* x    = (const float*)d_in[0];
    const float* y    = (const float*)d_in[1];
    const int* mask   = (const int*)d_in[2];
    const float* W    = (const float*)d_in[3];
    const float* bias = (const float*)d_in[4];
    float* out        = (float*)d_out;

    split_y<<<(BB * LYY * DD) / (256 * 4), 256>>>(y);
    proj_kernel<<<dim3(DD / 128, (BB * LXX) / 128), 256>>>(x, W, bias, 0);
    proj_kernel<<<dim3(DD / 128, (BB * LYY) / 128), 256>>>(y, W, bias, 1);

    cudaFuncSetAttribute(attn_mma_kernel,
                         cudaFuncAttributeMaxDynamicSharedMemorySize, SMTOT);
    attn_mma_kernel<<<dim3(LXX / 128, BB), 512, SMTOT>>>(mask, out);
}

// round 9
// speedup vs baseline: 2.0385x; 2.0385x over previous
#include <cuda_runtime.h>
#include <cuda_bf16.h>
#include <cstdint>

#define BB 8
#define LXX 2048
#define LYY 2048
#define DD 256

// ---------------- global scratch (no cudaMalloc allowed) ----------------
__device__ __nv_bfloat16 g_xp_h[BB * LXX * DD];
__device__ __nv_bfloat16 g_xp_l[BB * LXX * DD];
__device__ __nv_bfloat16 g_yp_h[BB * LYY * DD];
__device__ __nv_bfloat16 g_yp_l[BB * LYY * DD];
__device__ __nv_bfloat16 g_yv_h[BB * LYY * DD];   // raw y, bf16 hi
__device__ __nv_bfloat16 g_yv_l[BB * LYY * DD];   // raw y, bf16 lo

// ---------------- helpers (portable PTX only: sm_80-era) ----------------
__device__ __forceinline__ uint32_t smem_u32(const void* p) {
    uint32_t a;
    asm("{ .reg .u64 t; cvta.to.shared.u64 t, %1; cvt.u32.u64 %0, t; }" : "=r"(a) : "l"(p));
    return a;
}
__device__ __forceinline__ void cpa16(uint32_t s, const void* g) {
    asm volatile("cp.async.cg.shared.global [%0], [%1], 16;" :: "r"(s), "l"(g));
}
__device__ __forceinline__ void cpa4(uint32_t s, const void* g) {
    asm volatile("cp.async.ca.shared.global [%0], [%1], 4;" :: "r"(s), "l"(g));
}
#define CP_COMMIT() asm volatile("cp.async.commit_group;" ::: "memory")
#define CP_WAIT0()  asm volatile("cp.async.wait_group 0;" ::: "memory")
#define CP_WAIT1()  asm volatile("cp.async.wait_group 1;" ::: "memory")

__device__ __forceinline__ void ldsm4(uint32_t r[4], uint32_t a) {
    asm volatile("ldmatrix.sync.aligned.m8n8.x4.shared.b16 {%0,%1,%2,%3}, [%4];"
                 : "=r"(r[0]), "=r"(r[1]), "=r"(r[2]), "=r"(r[3]) : "r"(a));
}
__device__ __forceinline__ void ldsm4t(uint32_t r[4], uint32_t a) {
    asm volatile("ldmatrix.sync.aligned.m8n8.x4.trans.shared.b16 {%0,%1,%2,%3}, [%4];"
                 : "=r"(r[0]), "=r"(r[1]), "=r"(r[2]), "=r"(r[3]) : "r"(a));
}
__device__ __forceinline__ void mma16816(float c[4], const uint32_t a[4],
                                         uint32_t b0, uint32_t b1) {
    asm volatile(
        "mma.sync.aligned.m16n8k16.row.col.f32.bf16.bf16.f32 "
        "{%0,%1,%2,%3}, {%4,%5,%6,%7}, {%8,%9}, {%0,%1,%2,%3};"
        : "+f"(c[0]), "+f"(c[1]), "+f"(c[2]), "+f"(c[3])
        : "r"(a[0]), "r"(a[1]), "r"(a[2]), "r"(a[3]), "r"(b0), "r"(b1));
}
__device__ __forceinline__ uint32_t cvt2bf(float lo, float hi) {
    uint32_t r;
    asm("cvt.rn.bf16x2.f32 %0, %1, %2;" : "=r"(r) : "f"(hi), "f"(lo));
    return r;
}
__device__ __forceinline__ float exp2p(float t) {
    t = fmaxf(t, -126.0f);
    float n = rintf(t);
    float f = t - n;
    float p = fmaf(1.5403530e-4f, f, 1.3333558e-3f);
    p = fmaf(p, f, 9.6181290e-3f);
    p = fmaf(p, f, 5.5504109e-2f);
    p = fmaf(p, f, 2.4022651e-1f);
    p = fmaf(p, f, 6.9314718e-1f);
    p = fmaf(p, f, 1.0f);
    return p * __int_as_float(((int)n + 127) << 23);
}
#define L2E 1.4426950408889634f

// ---------------------------------------------------------------------------
// Projection (fp32 SIMT) -> bf16 hi/lo splits. C = relu(A @ W^T + b)
// ---------------------------------------------------------------------------
__global__ __launch_bounds__(256, 1)
void proj_kernel(const float* __restrict__ A,
                 const float* __restrict__ W,
                 const float* __restrict__ bias,
                 int which)
{
    __shared__ float As[16][132];
    __shared__ float Bs[16][132];

    const int tid = threadIdx.x;
    const int tx = tid & 15;
    const int ty = tid >> 4;
    const int row0 = blockIdx.y * 128;
    const int col0 = blockIdx.x * 128;

    __nv_bfloat16* __restrict__ Ch = which ? g_yp_h : g_xp_h;
    __nv_bfloat16* __restrict__ Cl = which ? g_yp_l : g_xp_l;

    float acc[8][8];
#pragma unroll
    for (int i = 0; i < 8; i++)
#pragma unroll
        for (int j = 0; j < 8; j++) acc[i][j] = 0.0f;

    for (int k0 = 0; k0 < DD; k0 += 16) {
#pragma unroll
        for (int e = 0; e < 8; e++) {
            int elem = tid + e * 256;
            int kk = elem & 15;
            int r  = elem >> 4;
            As[kk][r] = A[(size_t)(row0 + r) * DD + k0 + kk];
            Bs[kk][r] = W[(size_t)(col0 + r) * DD + k0 + kk];
        }
        __syncthreads();
#pragma unroll
        for (int kk = 0; kk < 16; kk++) {
            float4 a0 = *(const float4*)&As[kk][ty * 8];
            float4 a1 = *(const float4*)&As[kk][ty * 8 + 4];
            float4 b0 = *(const float4*)&Bs[kk][tx * 8];
            float4 b1 = *(const float4*)&Bs[kk][tx * 8 + 4];
            float a[8] = {a0.x, a0.y, a0.z, a0.w, a1.x, a1.y, a1.z, a1.w};
            float bq[8] = {b0.x, b0.y, b0.z, b0.w, b1.x, b1.y, b1.z, b1.w};
#pragma unroll
            for (int i = 0; i < 8; i++)
#pragma unroll
                for (int j = 0; j < 8; j++)
                    acc[i][j] = fmaf(a[i], bq[j], acc[i][j]);
        }
        __syncthreads();
    }

    float bv[8];
#pragma unroll
    for (int j = 0; j < 8; j++) bv[j] = bias[col0 + tx * 8 + j];

#pragma unroll
    for (int i = 0; i < 8; i++) {
        int row = row0 + ty * 8 + i;
        __nv_bfloat16 hb[8], lb[8];
#pragma unroll
        for (int j = 0; j < 8; j++) {
            float v = fmaxf(acc[i][j] + bv[j], 0.0f);
            __nv_bfloat16 h = __float2bfloat16_rn(v);
            hb[j] = h;
            lb[j] = __float2bfloat16_rn(v - __bfloat162float(h));
        }
        size_t o = (size_t)row * DD + col0 + tx * 8;
        *(uint4*)&Ch[o] = *(uint4*)hb;
        *(uint4*)&Cl[o] = *(uint4*)lb;
    }
}

// ---------------------------------------------------------------------------
// Elementwise y -> bf16 hi/lo (natural [b][tok][d] layout)
// ---------------------------------------------------------------------------
__global__ __launch_bounds__(256)
void split_y(const float* __restrict__ y)
{
    size_t i = ((size_t)blockIdx.x * 256 + threadIdx.x) * 4;
    float4 v = *(const float4*)(y + i);
    float vv[4] = {v.x, v.y, v.z, v.w};
    __nv_bfloat16 h[4], l[4];
#pragma unroll
    for (int k = 0; k < 4; k++) {
        h[k] = __float2bfloat16_rn(vv[k]);
        l[k] = __float2bfloat16_rn(vv[k] - __bfloat162float(h[k]));
    }
    *(uint2*)&g_yv_h[i] = *(uint2*)h;
    *(uint2*)&g_yv_l[i] = *(uint2*)l;
}

// ---------------------------------------------------------------------------
// Fused mma.sync attention, 256 threads (8 warps), XTILE 128, JTILE 32.
// S phase: R6-proven (warp = 16 rows x 32 cols, 3-pass hh+hl+lh).
// PV phase: d-split — warp owns d32 slice over ALL 128 rows; P-hi exchanged
// through smem (2-pass PhVh + PhVl; Pl dropped, row sums taken over ROUNDED
// P so the rounding acts as self-canceling weight perturbation).
// Lifetime-split cp.async pipelining preserved.
// ---------------------------------------------------------------------------
#define SXSTR 528                       // 256 bf16 + 8 pad, bytes
#define SXH 0
#define SXL (SXH + 128 * SXSTR)
#define SBH (SXL + 128 * SXSTR)
#define SBL (SBH + 32 * SXSTR)
#define SVH (SBL + 32 * SXSTR)
#define SVL (SVH + 32 * SXSTR)
#define SPH (SVL + 32 * SXSTR)          // P hi: 128 rows x 80B = 10240
#define SSC (SPH + 128 * 80)            // per-row scale/inv: 128 floats
#define SMK (SSC + 512)                 // 32 ints
#define SMTOT (SMK + 128)
#define NT (LYY / 32)

__global__ __launch_bounds__(256, 1)
void attn_mma_kernel(const int* __restrict__ mask, float* __restrict__ out)
{
    extern __shared__ char smc[];
    const uint32_t sa = smem_u32(smc);
    const int tid  = threadIdx.x;
    const int w    = tid >> 5;
    const int lane = tid & 31;
    const int lr   = lane >> 2;          // frag row within 8
    const int tig  = lane & 3;           // frag col pair
    const int b    = blockIdx.y;
    const int x0   = blockIdx.x * 128;
    const int rw   = w * 16;

    const int* mB = mask + (size_t)b * LYY;
    const size_t gyB = (size_t)(b * LYY) * DD;
    const int pr = tid >> 3, pcb = tid & 7;     // prefetch row / chunk base

    auto issueYp = [&](int t) {
        size_t gro = gyB + (size_t)(t * 32 + pr) * DD;
        uint32_t o = sa + (uint32_t)(pr * SXSTR);
#pragma unroll
        for (int i = 0; i < 4; i++) {
            int c = pcb + 8 * i;
            cpa16(o + SBH + c * 16, g_yp_h + gro + c * 8);
            cpa16(o + SBL + c * 16, g_yp_l + gro + c * 8);
        }
        if (tid < 32) cpa4(sa + SMK + tid * 4, mB + t * 32 + tid);
    };
    auto issueYv = [&](int t) {
        size_t gro = gyB + (size_t)(t * 32 + pr) * DD;
        uint32_t o = sa + (uint32_t)(pr * SXSTR);
#pragma unroll
        for (int i = 0; i < 4; i++) {
            int c = pcb + 8 * i;
            cpa16(o + SVH + c * 16, g_yv_h + gro + c * 8);
            cpa16(o + SVL + c * 16, g_yv_l + gro + c * 8);
        }
    };

    // ---- prologue: X tile (group 0), Yp(0) (group 1), yV(0) (group 2) ----
    {
        int r = tid >> 1;
        const __nv_bfloat16* srch = g_xp_h + (size_t)(b * LXX + x0 + r) * DD;
        const __nv_bfloat16* srcl = g_xp_l + (size_t)(b * LXX + x0 + r) * DD;
        uint32_t dh = sa + SXH + r * SXSTR;
        uint32_t dl = sa + SXL + r * SXSTR;
#pragma unroll
        for (int i = 0; i < 16; i++) {
            int c = (tid & 1) + 2 * i;
            cpa16(dh + c * 16, srch + c * 8);
            cpa16(dl + c * 16, srcl + c * 8);
        }
    }
    CP_COMMIT();
    issueYp(0);
    CP_COMMIT();
    issueYv(0);
    CP_COMMIT();

    const int* smk = (const int*)(smc + SMK);
    float* sSC = (float*)(smc + SSC);

    // O: warp's d32 slice over all 128 rows: [m-group 0..7][d-frag 0..3]
    float O[32][4];
#pragma unroll
    for (int i = 0; i < 32; i++) { O[i][0] = O[i][1] = O[i][2] = O[i][3] = 0.f; }
    float m0 = -1e30f, m1 = -1e30f, l0 = 0.f, l1 = 0.f;

    // ldmatrix addresses
    const uint32_t aA  = sa + SXH + (rw + (lane & 7) + ((lane >> 3) & 1) * 8) * SXSTR
                       + (lane >> 4) * 16;
    const uint32_t aAl = aA + (uint32_t)(SXL - SXH);
    const uint32_t aB  = sa + SBH + ((lane & 7) + ((lane < 16) ? 0 : 8)) * SXSTR
                       + ((lane >> 3) & 1) * 16;
    const uint32_t aBl = aB + (uint32_t)(SBL - SBH);
    // PV: P frags (A-role, rows=m stride 80) and V frags (B-role, d-slice w*32)
    const uint32_t aP  = sa + SPH + ((lane & 7) + ((lane >> 3) & 1) * 8) * 80
                       + (lane >> 4) * 16;
    const uint32_t aVd = sa + SVH + ((lane & 7) + ((lane >> 3) & 1) * 8) * SXSTR
                       + w * 64 + ((lane < 16) ? 0 : 16);
    const uint32_t aVdl = aVd + (uint32_t)(SVL - SVH);

    const int r0 = rw + lr, r1 = rw + lr + 8;

#pragma unroll 1
    for (int t = 0; t < NT; t++) {
        // wait: X + Yp(t) arrived (yV(t) may still be pending)
        CP_WAIT1();
        __syncthreads();

        // ---- S = Xp @ Yp^T (hh + hl + lh), 16 rows x 32 cols per warp ----
        float sf[4][4];
#pragma unroll
        for (int nt = 0; nt < 4; nt++)
#pragma unroll
            for (int i = 0; i < 4; i++) sf[nt][i] = 0.f;

#pragma unroll 4
        for (int kk = 0; kk < 16; kk++) {
            uint32_t ah[4], al[4], bh[4], bl[4];
            ldsm4(ah, aA  + kk * 32);
            ldsm4(al, aAl + kk * 32);
            // j 0..15
            ldsm4(bh, aB  + kk * 32);
            ldsm4(bl, aBl + kk * 32);
            mma16816(sf[0], ah, bh[0], bh[1]);
            mma16816(sf[0], ah, bl[0], bl[1]);
            mma16816(sf[0], al, bh[0], bh[1]);
            mma16816(sf[1], ah, bh[2], bh[3]);
            mma16816(sf[1], ah, bl[2], bl[3]);
            mma16816(sf[1], al, bh[2], bh[3]);
            // j 16..31
            ldsm4(bh, aB  + 16 * SXSTR + kk * 32);
            ldsm4(bl, aBl + 16 * SXSTR + kk * 32);
            mma16816(sf[2], ah, bh[0], bh[1]);
            mma16816(sf[2], ah, bl[0], bl[1]);
            mma16816(sf[2], al, bh[0], bh[1]);
            mma16816(sf[3], ah, bh[2], bh[3]);
            mma16816(sf[3], ah, bl[2], bl[3]);
            mma16816(sf[3], al, bh[2], bh[3]);
        }

        // ---- mask + online softmax ----
        float mx0 = -1e30f, mx1 = -1e30f;
#pragma unroll
        for (int nt = 0; nt < 4; nt++) {
            int j = 8 * nt + 2 * tig;
            if (smk[j])     { sf[nt][0] = -1e30f; sf[nt][2] = -1e30f; }
            if (smk[j + 1]) { sf[nt][1] = -1e30f; sf[nt][3] = -1e30f; }
            mx0 = fmaxf(mx0, fmaxf(sf[nt][0], sf[nt][1]));
            mx1 = fmaxf(mx1, fmaxf(sf[nt][2], sf[nt][3]));
        }
        mx0 = fmaxf(mx0, __shfl_xor_sync(0xffffffffu, mx0, 1));
        mx0 = fmaxf(mx0, __shfl_xor_sync(0xffffffffu, mx0, 2));
        mx1 = fmaxf(mx1, __shfl_xor_sync(0xffffffffu, mx1, 1));
        mx1 = fmaxf(mx1, __shfl_xor_sync(0xffffffffu, mx1, 2));

        float mn0 = fmaxf(m0, mx0), mn1 = fmaxf(m1, mx1);
        float sc0 = exp2p((m0 - mn0) * L2E);
        float sc1 = exp2p((m1 - mn1) * L2E);
        m0 = mn0; m1 = mn1;

        // P (rounded to bf16); row sums over the ROUNDED values
        uint32_t ph[8];
        float rs0 = 0.f, rs1 = 0.f;
#pragma unroll
        for (int nt = 0; nt < 4; nt++) {
            float p00 = exp2p((sf[nt][0] - mn0) * L2E);
            float p01 = exp2p((sf[nt][1] - mn0) * L2E);
            float p10 = exp2p((sf[nt][2] - mn1) * L2E);
            float p11 = exp2p((sf[nt][3] - mn1) * L2E);
            uint32_t h0 = cvt2bf(p00, p01);
            uint32_t h1 = cvt2bf(p10, p11);
            ph[nt * 2]     = h0;
            ph[nt * 2 + 1] = h1;
            rs0 += __uint_as_float(h0 << 16) + __uint_as_float(h0 & 0xffff0000u);
            rs1 += __uint_as_float(h1 << 16) + __uint_as_float(h1 & 0xffff0000u);
        }
        rs0 += __shfl_xor_sync(0xffffffffu, rs0, 1);
        rs0 += __shfl_xor_sync(0xffffffffu, rs0, 2);
        rs1 += __shfl_xor_sync(0xffffffffu, rs1, 1);
        rs1 += __shfl_xor_sync(0xffffffffu, rs1, 2);
        l0 = l0 * sc0 + rs0;
        l1 = l1 * sc1 + rs1;

        // write P-hi to smem (rows=m, cols=k32 of this tile) + sc broadcast
#pragma unroll
        for (int nt = 0; nt < 4; nt++) {
            *(uint32_t*)(smc + SPH + r0 * 80 + 16 * nt + 4 * tig) = ph[nt * 2];
            *(uint32_t*)(smc + SPH + r1 * 80 + 16 * nt + 4 * tig) = ph[nt * 2 + 1];
        }
        if (tig == 0) { sSC[r0] = sc0; sSC[r1] = sc1; }
        __syncthreads();    // (B) P + sc visible; Yp/mask dead

        // overlap: Yp(t+1) flies during rescale + PV
        if (t < NT - 1) issueYp(t + 1);
        CP_COMMIT();

        // O rescale: per-row factors from smem
#pragma unroll
        for (int mg = 0; mg < 8; mg++) {
            float sA = sSC[mg * 16 + lr];
            float sB = sSC[mg * 16 + lr + 8];
#pragma unroll
            for (int df = 0; df < 4; df++) {
                O[mg * 4 + df][0] *= sA; O[mg * 4 + df][1] *= sA;
                O[mg * 4 + df][2] *= sB; O[mg * 4 + df][3] *= sB;
            }
        }

        // wait for yV(t); last iter drain all
        if (t < NT - 1) { CP_WAIT1(); } else { CP_WAIT0(); }
        __syncthreads();    // (C)

        // ---- PV: O[all rows, d32 slice] += Ph @ (Vh + Vl) ----
#pragma unroll
        for (int k = 0; k < 2; k++) {
            uint32_t vh0[4], vl0[4], vh1[4], vl1[4];
            ldsm4t(vh0, aVd  + k * 16 * SXSTR);
            ldsm4t(vh1, aVd  + k * 16 * SXSTR + 32);
            ldsm4t(vl0, aVdl + k * 16 * SXSTR);
            ldsm4t(vl1, aVdl + k * 16 * SXSTR + 32);
#pragma unroll
            for (int mg = 0; mg < 8; mg++) {
                uint32_t pA[4];
                ldsm4(pA, aP + mg * 1280 + k * 32);
                mma16816(O[mg * 4 + 0], pA, vh0[0], vh0[1]);
                mma16816(O[mg * 4 + 0], pA, vl0[0], vl0[1]);
                mma16816(O[mg * 4 + 1], pA, vh0[2], vh0[3]);
                mma16816(O[mg * 4 + 1], pA, vl0[2], vl0[3]);
                mma16816(O[mg * 4 + 2], pA, vh1[0], vh1[1]);
                mma16816(O[mg * 4 + 2], pA, vl1[0], vl1[1]);
                mma16816(O[mg * 4 + 3], pA, vh1[2], vh1[3]);
                mma16816(O[mg * 4 + 3], pA, vl1[2], vl1[3]);
            }
        }
        __syncthreads();    // (D) yV + P reads done

        if (t < NT - 1) issueYv(t + 1);
        CP_COMMIT();
    }

    // ---- epilogue: broadcast 1/l per row, normalize + store d-slice ----
    if (tig == 0) { sSC[r0] = 1.0f / l0; sSC[r1] = 1.0f / l1; }
    __syncthreads();
#pragma unroll
    for (int mg = 0; mg < 8; mg++) {
        float iA = sSC[mg * 16 + lr];
        float iB = sSC[mg * 16 + lr + 8];
        float* oA = out + (size_t)(b * LXX + x0 + mg * 16 + lr) * DD + w * 32;
        float* oB = oA + 8 * DD;
#pragma unroll
        for (int df = 0; df < 4; df++) {
            int c = df * 8 + tig * 2;
            *(float2*)(oA + c) = make_float2(O[mg * 4 + df][0] * iA,
                                             O[mg * 4 + df][1] * iA);
            *(float2*)(oB + c) = make_float2(O[mg * 4 + df][2] * iB,
                                             O[mg * 4 + df][3] * iB);
        }
    }
}

// ---------------------------------------------------------------------------
extern "C" void kernel_launch(void* const* d_in, const int* in_sizes, int n_in,
                              void* d_out, int out_size)
{
    const float* x    = (const float*)d_in[0];
    const float* y    = (const float*)d_in[1];
    const int* mask   = (const int*)d_in[2];
    const float* W    = (const float*)d_in[3];
    const float* bias = (const float*)d_in[4];
    float* out        = (float*)d_out;

    split_y<<<(BB * LYY * DD) / (256 * 4), 256>>>(y);
    proj_kernel<<<dim3(DD / 128, (BB * LXX) / 128), 256>>>(x, W, bias, 0);
    proj_kernel<<<dim3(DD / 128, (BB * LYY) / 128), 256>>>(y, W, bias, 1);

    cudaFuncSetAttribute(attn_mma_kernel,
                         cudaFuncAttributeMaxDynamicSharedMemorySize, SMTOT);
    attn_mma_kernel<<<dim3(LXX / 128, BB), 256, SMTOT>>>(mask, out);
}

// round 10
// speedup vs baseline: 2.3993x; 1.1770x over previous
#include <cuda_runtime.h>
#include <cuda_bf16.h>
#include <cstdint>

#define BB 8
#define LXX 2048
#define LYY 2048
#define DD 256

// ---------------- global scratch (no cudaMalloc allowed) ----------------
__device__ __nv_bfloat16 g_x_h[BB * LXX * DD];    // raw x, bf16 hi/lo
__device__ __nv_bfloat16 g_x_l[BB * LXX * DD];
__device__ __nv_bfloat16 g_xp_h[BB * LXX * DD];
__device__ __nv_bfloat16 g_xp_l[BB * LXX * DD];
__device__ __nv_bfloat16 g_yp_h[BB * LYY * DD];
__device__ __nv_bfloat16 g_yp_l[BB * LYY * DD];
__device__ __nv_bfloat16 g_yv_h[BB * LYY * DD];   // raw y, bf16 hi/lo
__device__ __nv_bfloat16 g_yv_l[BB * LYY * DD];
__device__ __nv_bfloat16 g_W_h[DD * DD];
__device__ __nv_bfloat16 g_W_l[DD * DD];

// ---------------- helpers (portable PTX only: sm_80-era) ----------------
__device__ __forceinline__ uint32_t smem_u32(const void* p) {
    uint32_t a;
    asm("{ .reg .u64 t; cvta.to.shared.u64 t, %1; cvt.u32.u64 %0, t; }" : "=r"(a) : "l"(p));
    return a;
}
__device__ __forceinline__ void cpa16(uint32_t s, const void* g) {
    asm volatile("cp.async.cg.shared.global [%0], [%1], 16;" :: "r"(s), "l"(g));
}
__device__ __forceinline__ void cpa4(uint32_t s, const void* g) {
    asm volatile("cp.async.ca.shared.global [%0], [%1], 4;" :: "r"(s), "l"(g));
}
#define CP_COMMIT() asm volatile("cp.async.commit_group;" ::: "memory")
#define CP_WAIT0()  asm volatile("cp.async.wait_group 0;" ::: "memory")
#define CP_WAIT1()  asm volatile("cp.async.wait_group 1;" ::: "memory")

__device__ __forceinline__ void ldsm4(uint32_t r[4], uint32_t a) {
    asm volatile("ldmatrix.sync.aligned.m8n8.x4.shared.b16 {%0,%1,%2,%3}, [%4];"
                 : "=r"(r[0]), "=r"(r[1]), "=r"(r[2]), "=r"(r[3]) : "r"(a));
}
__device__ __forceinline__ void ldsm4t(uint32_t r[4], uint32_t a) {
    asm volatile("ldmatrix.sync.aligned.m8n8.x4.trans.shared.b16 {%0,%1,%2,%3}, [%4];"
                 : "=r"(r[0]), "=r"(r[1]), "=r"(r[2]), "=r"(r[3]) : "r"(a));
}
__device__ __forceinline__ void mma16816(float c[4], const uint32_t a[4],
                                         uint32_t b0, uint32_t b1) {
    asm volatile(
        "mma.sync.aligned.m16n8k16.row.col.f32.bf16.bf16.f32 "
        "{%0,%1,%2,%3}, {%4,%5,%6,%7}, {%8,%9}, {%0,%1,%2,%3};"
        : "+f"(c[0]), "+f"(c[1]), "+f"(c[2]), "+f"(c[3])
        : "r"(a[0]), "r"(a[1]), "r"(a[2]), "r"(a[3]), "r"(b0), "r"(b1));
}
__device__ __forceinline__ uint32_t cvt2bf(float lo, float hi) {
    uint32_t r;
    asm("cvt.rn.bf16x2.f32 %0, %1, %2;" : "=r"(r) : "f"(hi), "f"(lo));
    return r;
}
__device__ __forceinline__ float exp2p(float t) {
    t = fmaxf(t, -126.0f);
    float n = rintf(t);
    float f = t - n;
    float p = fmaf(1.5403530e-4f, f, 1.3333558e-3f);
    p = fmaf(p, f, 9.6181290e-3f);
    p = fmaf(p, f, 5.5504109e-2f);
    p = fmaf(p, f, 2.4022651e-1f);
    p = fmaf(p, f, 6.9314718e-1f);
    p = fmaf(p, f, 1.0f);
    return p * __int_as_float(((int)n + 127) << 23);
}
#define L2E 1.4426950408889634f

// ---------------------------------------------------------------------------
// Elementwise bf16 hi/lo splitters
// ---------------------------------------------------------------------------
__global__ __launch_bounds__(256)
void split_W(const float* __restrict__ W)
{
    size_t i = ((size_t)blockIdx.x * 256 + threadIdx.x) * 4;
    float4 v = *(const float4*)(W + i);
    float vv[4] = {v.x, v.y, v.z, v.w};
    __nv_bfloat16 h[4], l[4];
#pragma unroll
    for (int k = 0; k < 4; k++) {
        h[k] = __float2bfloat16_rn(vv[k]);
        l[k] = __float2bfloat16_rn(vv[k] - __bfloat162float(h[k]));
    }
    *(uint2*)&g_W_h[i] = *(uint2*)h;
    *(uint2*)&g_W_l[i] = *(uint2*)l;
}
__global__ __launch_bounds__(256)
void split_x(const float* __restrict__ x)
{
    size_t i = ((size_t)blockIdx.x * 256 + threadIdx.x) * 4;
    float4 v = *(const float4*)(x + i);
    float vv[4] = {v.x, v.y, v.z, v.w};
    __nv_bfloat16 h[4], l[4];
#pragma unroll
    for (int k = 0; k < 4; k++) {
        h[k] = __float2bfloat16_rn(vv[k]);
        l[k] = __float2bfloat16_rn(vv[k] - __bfloat162float(h[k]));
    }
    *(uint2*)&g_x_h[i] = *(uint2*)h;
    *(uint2*)&g_x_l[i] = *(uint2*)l;
}
__global__ __launch_bounds__(256)
void split_y(const float* __restrict__ y)
{
    size_t i = ((size_t)blockIdx.x * 256 + threadIdx.x) * 4;
    float4 v = *(const float4*)(y + i);
    float vv[4] = {v.x, v.y, v.z, v.w};
    __nv_bfloat16 h[4], l[4];
#pragma unroll
    for (int k = 0; k < 4; k++) {
        h[k] = __float2bfloat16_rn(vv[k]);
        l[k] = __float2bfloat16_rn(vv[k] - __bfloat162float(h[k]));
    }
    *(uint2*)&g_yv_h[i] = *(uint2*)h;
    *(uint2*)&g_yv_l[i] = *(uint2*)l;
}

// ---------------------------------------------------------------------------
// Tensor-core projection: C = relu(A @ W^T + b) -> bf16 h/l splits.
// Inputs pre-split bf16 (x via split_x, y via split_y = g_yv, W via split_W).
// CTA = 128 rows x 128 cols. W-half RESIDENT in smem; A streamed in k32
// double-buffered stages. 3-pass hh+hl+lh. Frag layouts = attn S phase.
// Grid: (row_block 0..255, col_half 0..1). Rows [0,16384)=x, rest=y.
// ---------------------------------------------------------------------------
#define QW_H 0
#define QW_L 67584          // 128 x 528
#define QA_H 135168         // 2 stages x 10240 (128 rows x 80B)
#define QA_L 155648
#define QTOT 176128
#define QASTR 80

__global__ __launch_bounds__(256, 1)
void proj_mma_kernel(const float* __restrict__ bias)
{
    extern __shared__ char smc[];
    const uint32_t sa = smem_u32(smc);
    const int tid  = threadIdx.x;
    const int w    = tid >> 5;
    const int lane = tid & 31;
    const int lr   = lane >> 2;
    const int tig  = lane & 3;
    const int rw   = w * 16;
    const int wcol0 = blockIdx.y * 128;
    const int row0  = blockIdx.x * 128;          // 0..32767
    const bool isx  = row0 < BB * LXX;
    const int arow0 = isx ? row0 : row0 - BB * LXX;

    const __nv_bfloat16* __restrict__ Ah = isx ? g_x_h : g_yv_h;
    const __nv_bfloat16* __restrict__ Al = isx ? g_x_l : g_yv_l;
    __nv_bfloat16* __restrict__ Ch = isx ? g_xp_h : g_yp_h;
    __nv_bfloat16* __restrict__ Cl = isx ? g_xp_l : g_yp_l;

    // ---- resident W half (h+l) + first A stage, one cp.async group ----
    {
        int r = tid >> 1, hb = (tid & 1) * 16;
        const __nv_bfloat16* wh = g_W_h + (size_t)(wcol0 + r) * DD + hb * 8;
        const __nv_bfloat16* wl = g_W_l + (size_t)(wcol0 + r) * DD + hb * 8;
        uint32_t dh = sa + QW_H + r * 528 + hb * 16;
        uint32_t dl = sa + QW_L + r * 528 + hb * 16;
#pragma unroll
        for (int i = 0; i < 16; i++) {
            cpa16(dh + i * 16, wh + i * 8);
            cpa16(dl + i * 16, wl + i * 8);
        }
    }
    auto prefA = [&](int s, int kc) {
        int r = tid >> 1, hb = tid & 1;
        const __nv_bfloat16* ph = Ah + (size_t)(arow0 + r) * DD + kc * 32 + hb * 16;
        const __nv_bfloat16* pl = Al + (size_t)(arow0 + r) * DD + kc * 32 + hb * 16;
        uint32_t dh = sa + QA_H + s * 10240 + r * QASTR + hb * 32;
        uint32_t dl = sa + QA_L + s * 10240 + r * QASTR + hb * 32;
        cpa16(dh, ph); cpa16(dh + 16, ph + 8);
        cpa16(dl, pl); cpa16(dl + 16, pl + 8);
    };
    prefA(0, 0);
    CP_COMMIT();

    float O[16][4];
#pragma unroll
    for (int i = 0; i < 16; i++) { O[i][0] = O[i][1] = O[i][2] = O[i][3] = 0.f; }

    const uint32_t aA  = sa + QA_H + (rw + (lane & 7) + ((lane >> 3) & 1) * 8) * QASTR
                       + (lane >> 4) * 16;
    const uint32_t aAl = aA + (uint32_t)(QA_L - QA_H);
    const uint32_t aW  = sa + QW_H + ((lane & 7) + ((lane < 16) ? 0 : 8)) * 528
                       + ((lane >> 3) & 1) * 16;
    const uint32_t aWl = aW + (uint32_t)(QW_L - QW_H);

#pragma unroll 1
    for (int kc = 0; kc < 8; kc++) {
        const int s = kc & 1;
        if (kc < 7) { prefA(s ^ 1, kc + 1); CP_COMMIT(); CP_WAIT1(); }
        else        { CP_WAIT0(); }
        __syncthreads();

        const uint32_t sOff = (uint32_t)(s * 10240);
#pragma unroll
        for (int kk = 0; kk < 2; kk++) {
            uint32_t ah[4], al[4];
            ldsm4(ah, aA  + sOff + kk * 32);
            ldsm4(al, aAl + sOff + kk * 32);
            const uint32_t kOff = (uint32_t)(kc * 64 + kk * 32);
#pragma unroll
            for (int g = 0; g < 8; g++) {
                uint32_t bh[4], bl[4];
                ldsm4(bh, aW  + g * (16 * 528) + kOff);
                ldsm4(bl, aWl + g * (16 * 528) + kOff);
                mma16816(O[2 * g],     ah, bh[0], bh[1]);
                mma16816(O[2 * g],     ah, bl[0], bl[1]);
                mma16816(O[2 * g],     al, bh[0], bh[1]);
                mma16816(O[2 * g + 1], ah, bh[2], bh[3]);
                mma16816(O[2 * g + 1], ah, bl[2], bl[3]);
                mma16816(O[2 * g + 1], al, bh[2], bh[3]);
            }
        }
        __syncthreads();
    }

    // ---- epilogue: bias + relu + h/l split + store ----
    const int r0g = arow0 + rw + lr;
#pragma unroll
    for (int f = 0; f < 16; f++) {
        int c = wcol0 + f * 8 + tig * 2;
        float b0 = __ldg(bias + c), b1 = __ldg(bias + c + 1);
        // row r0g
        {
            float v0 = fmaxf(O[f][0] + b0, 0.f), v1 = fmaxf(O[f][1] + b1, 0.f);
            uint32_t h = cvt2bf(v0, v1);
            float q0 = v0 - __uint_as_float(h << 16);
            float q1 = v1 - __uint_as_float(h & 0xffff0000u);
            uint32_t l = cvt2bf(q0, q1);
            size_t o = (size_t)r0g * DD + c;
            *(uint32_t*)&Ch[o] = h;
            *(uint32_t*)&Cl[o] = l;
        }
        // row r0g + 8
        {
            float v0 = fmaxf(O[f][2] + b0, 0.f), v1 = fmaxf(O[f][3] + b1, 0.f);
            uint32_t h = cvt2bf(v0, v1);
            float q0 = v0 - __uint_as_float(h << 16);
            float q1 = v1 - __uint_as_float(h & 0xffff0000u);
            uint32_t l = cvt2bf(q0, q1);
            size_t o = (size_t)(r0g + 8) * DD + c;
            *(uint32_t*)&Ch[o] = h;
            *(uint32_t*)&Cl[o] = l;
        }
    }
}

// ---------------------------------------------------------------------------
// Fused mma.sync attention (R9, unchanged): 256 threads, XTILE 128, JTILE 32.
// S phase: warp = 16 rows x 32 cols, 3-pass hh+hl+lh.
// PV phase: d-split, P-hi smem exchange, 2-pass PhVh+PhVl (sums over rounded P).
// ---------------------------------------------------------------------------
#define SXSTR 528
#define SXH 0
#define SXL (SXH + 128 * SXSTR)
#define SBH (SXL + 128 * SXSTR)
#define SBL (SBH + 32 * SXSTR)
#define SVH (SBL + 32 * SXSTR)
#define SVL (SVH + 32 * SXSTR)
#define SPH (SVL + 32 * SXSTR)
#define SSC (SPH + 128 * 80)
#define SMK (SSC + 512)
#define SMTOT (SMK + 128)
#define NT (LYY / 32)

__global__ __launch_bounds__(256, 1)
void attn_mma_kernel(const int* __restrict__ mask, float* __restrict__ out)
{
    extern __shared__ char smc[];
    const uint32_t sa = smem_u32(smc);
    const int tid  = threadIdx.x;
    const int w    = tid >> 5;
    const int lane = tid & 31;
    const int lr   = lane >> 2;
    const int tig  = lane & 3;
    const int b    = blockIdx.y;
    const int x0   = blockIdx.x * 128;
    const int rw   = w * 16;

    const int* mB = mask + (size_t)b * LYY;
    const size_t gyB = (size_t)(b * LYY) * DD;
    const int pr = tid >> 3, pcb = tid & 7;

    auto issueYp = [&](int t) {
        size_t gro = gyB + (size_t)(t * 32 + pr) * DD;
        uint32_t o = sa + (uint32_t)(pr * SXSTR);
#pragma unroll
        for (int i = 0; i < 4; i++) {
            int c = pcb + 8 * i;
            cpa16(o + SBH + c * 16, g_yp_h + gro + c * 8);
            cpa16(o + SBL + c * 16, g_yp_l + gro + c * 8);
        }
        if (tid < 32) cpa4(sa + SMK + tid * 4, mB + t * 32 + tid);
    };
    auto issueYv = [&](int t) {
        size_t gro = gyB + (size_t)(t * 32 + pr) * DD;
        uint32_t o = sa + (uint32_t)(pr * SXSTR);
#pragma unroll
        for (int i = 0; i < 4; i++) {
            int c = pcb + 8 * i;
            cpa16(o + SVH + c * 16, g_yv_h + gro + c * 8);
            cpa16(o + SVL + c * 16, g_yv_l + gro + c * 8);
        }
    };

    {
        int r = tid >> 1;
        const __nv_bfloat16* srch = g_xp_h + (size_t)(b * LXX + x0 + r) * DD;
        const __nv_bfloat16* srcl = g_xp_l + (size_t)(b * LXX + x0 + r) * DD;
        uint32_t dh = sa + SXH + r * SXSTR;
        uint32_t dl = sa + SXL + r * SXSTR;
#pragma unroll
        for (int i = 0; i < 16; i++) {
            int c = (tid & 1) + 2 * i;
            cpa16(dh + c * 16, srch + c * 8);
            cpa16(dl + c * 16, srcl + c * 8);
        }
    }
    CP_COMMIT();
    issueYp(0);
    CP_COMMIT();
    issueYv(0);
    CP_COMMIT();

    const int* smk = (const int*)(smc + SMK);
    float* sSC = (float*)(smc + SSC);

    float O[32][4];
#pragma unroll
    for (int i = 0; i < 32; i++) { O[i][0] = O[i][1] = O[i][2] = O[i][3] = 0.f; }
    float m0 = -1e30f, m1 = -1e30f, l0 = 0.f, l1 = 0.f;

    const uint32_t aA  = sa + SXH + (rw + (lane & 7) + ((lane >> 3) & 1) * 8) * SXSTR
                       + (lane >> 4) * 16;
    const uint32_t aAl = aA + (uint32_t)(SXL - SXH);
    const uint32_t aB  = sa + SBH + ((lane & 7) + ((lane < 16) ? 0 : 8)) * SXSTR
                       + ((lane >> 3) & 1) * 16;
    const uint32_t aBl = aB + (uint32_t)(SBL - SBH);
    const uint32_t aP  = sa + SPH + ((lane & 7) + ((lane >> 3) & 1) * 8) * 80
                       + (lane >> 4) * 16;
    const uint32_t aVd = sa + SVH + ((lane & 7) + ((lane >> 3) & 1) * 8) * SXSTR
                       + w * 64 + ((lane < 16) ? 0 : 16);
    const uint32_t aVdl = aVd + (uint32_t)(SVL - SVH);

    const int r0 = rw + lr, r1 = rw + lr + 8;

#pragma unroll 1
    for (int t = 0; t < NT; t++) {
        CP_WAIT1();
        __syncthreads();

        float sf[4][4];
#pragma unroll
        for (int nt = 0; nt < 4; nt++)
#pragma unroll
            for (int i = 0; i < 4; i++) sf[nt][i] = 0.f;

#pragma unroll 4
        for (int kk = 0; kk < 16; kk++) {
            uint32_t ah[4], al[4], bh[4], bl[4];
            ldsm4(ah, aA  + kk * 32);
            ldsm4(al, aAl + kk * 32);
            ldsm4(bh, aB  + kk * 32);
            ldsm4(bl, aBl + kk * 32);
            mma16816(sf[0], ah, bh[0], bh[1]);
            mma16816(sf[0], ah, bl[0], bl[1]);
            mma16816(sf[0], al, bh[0], bh[1]);
            mma16816(sf[1], ah, bh[2], bh[3]);
            mma16816(sf[1], ah, bl[2], bl[3]);
            mma16816(sf[1], al, bh[2], bh[3]);
            ldsm4(bh, aB  + 16 * SXSTR + kk * 32);
            ldsm4(bl, aBl + 16 * SXSTR + kk * 32);
            mma16816(sf[2], ah, bh[0], bh[1]);
            mma16816(sf[2], ah, bl[0], bl[1]);
            mma16816(sf[2], al, bh[0], bh[1]);
            mma16816(sf[3], ah, bh[2], bh[3]);
            mma16816(sf[3], ah, bl[2], bl[3]);
            mma16816(sf[3], al, bh[2], bh[3]);
        }

        float mx0 = -1e30f, mx1 = -1e30f;
#pragma unroll
        for (int nt = 0; nt < 4; nt++) {
            int j = 8 * nt + 2 * tig;
            if (smk[j])     { sf[nt][0] = -1e30f; sf[nt][2] = -1e30f; }
            if (smk[j + 1]) { sf[nt][1] = -1e30f; sf[nt][3] = -1e30f; }
            mx0 = fmaxf(mx0, fmaxf(sf[nt][0], sf[nt][1]));
            mx1 = fmaxf(mx1, fmaxf(sf[nt][2], sf[nt][3]));
        }
        mx0 = fmaxf(mx0, __shfl_xor_sync(0xffffffffu, mx0, 1));
        mx0 = fmaxf(mx0, __shfl_xor_sync(0xffffffffu, mx0, 2));
        mx1 = fmaxf(mx1, __shfl_xor_sync(0xffffffffu, mx1, 1));
        mx1 = fmaxf(mx1, __shfl_xor_sync(0xffffffffu, mx1, 2));

        float mn0 = fmaxf(m0, mx0), mn1 = fmaxf(m1, mx1);
        float sc0 = exp2p((m0 - mn0) * L2E);
        float sc1 = exp2p((m1 - mn1) * L2E);
        m0 = mn0; m1 = mn1;

        uint32_t ph[8];
        float rs0 = 0.f, rs1 = 0.f;
#pragma unroll
        for (int nt = 0; nt < 4; nt++) {
            float p00 = exp2p((sf[nt][0] - mn0) * L2E);
            float p01 = exp2p((sf[nt][1] - mn0) * L2E);
            float p10 = exp2p((sf[nt][2] - mn1) * L2E);
            float p11 = exp2p((sf[nt][3] - mn1) * L2E);
            uint32_t h0 = cvt2bf(p00, p01);
            uint32_t h1 = cvt2bf(p10, p11);
            ph[nt * 2]     = h0;
            ph[nt * 2 + 1] = h1;
            rs0 += __uint_as_float(h0 << 16) + __uint_as_float(h0 & 0xffff0000u);
            rs1 += __uint_as_float(h1 << 16) + __uint_as_float(h1 & 0xffff0000u);
        }
        rs0 += __shfl_xor_sync(0xffffffffu, rs0, 1);
        rs0 += __shfl_xor_sync(0xffffffffu, rs0, 2);
        rs1 += __shfl_xor_sync(0xffffffffu, rs1, 1);
        rs1 += __shfl_xor_sync(0xffffffffu, rs1, 2);
        l0 = l0 * sc0 + rs0;
        l1 = l1 * sc1 + rs1;

#pragma unroll
        for (int nt = 0; nt < 4; nt++) {
            *(uint32_t*)(smc + SPH + r0 * 80 + 16 * nt + 4 * tig) = ph[nt * 2];
            *(uint32_t*)(smc + SPH + r1 * 80 + 16 * nt + 4 * tig) = ph[nt * 2 + 1];
        }
        if (tig == 0) { sSC[r0] = sc0; sSC[r1] = sc1; }
        __syncthreads();

        if (t < NT - 1) issueYp(t + 1);
        CP_COMMIT();

#pragma unroll
        for (int mg = 0; mg < 8; mg++) {
            float sA = sSC[mg * 16 + lr];
            float sB = sSC[mg * 16 + lr + 8];
#pragma unroll
            for (int df = 0; df < 4; df++) {
                O[mg * 4 + df][0] *= sA; O[mg * 4 + df][1] *= sA;
                O[mg * 4 + df][2] *= sB; O[mg * 4 + df][3] *= sB;
            }
        }

        if (t < NT - 1) { CP_WAIT1(); } else { CP_WAIT0(); }
        __syncthreads();

#pragma unroll
        for (int k = 0; k < 2; k++) {
            uint32_t vh0[4], vl0[4], vh1[4], vl1[4];
            ldsm4t(vh0, aVd  + k * 16 * SXSTR);
            ldsm4t(vh1, aVd  + k * 16 * SXSTR + 32);
            ldsm4t(vl0, aVdl + k * 16 * SXSTR);
            ldsm4t(vl1, aVdl + k * 16 * SXSTR + 32);
#pragma unroll
            for (int mg = 0; mg < 8; mg++) {
                uint32_t pA[4];
                ldsm4(pA, aP + mg * 1280 + k * 32);
                mma16816(O[mg * 4 + 0], pA, vh0[0], vh0[1]);
                mma16816(O[mg * 4 + 0], pA, vl0[0], vl0[1]);
                mma16816(O[mg * 4 + 1], pA, vh0[2], vh0[3]);
                mma16816(O[mg * 4 + 1], pA, vl0[2], vl0[3]);
                mma16816(O[mg * 4 + 2], pA, vh1[0], vh1[1]);
                mma16816(O[mg * 4 + 2], pA, vl1[0], vl1[1]);
                mma16816(O[mg * 4 + 3], pA, vh1[2], vh1[3]);
                mma16816(O[mg * 4 + 3], pA, vl1[2], vl1[3]);
            }
        }
        __syncthreads();

        if (t < NT - 1) issueYv(t + 1);
        CP_COMMIT();
    }

    if (tig == 0) { sSC[r0] = 1.0f / l0; sSC[r1] = 1.0f / l1; }
    __syncthreads();
#pragma unroll
    for (int mg = 0; mg < 8; mg++) {
        float iA = sSC[mg * 16 + lr];
        float iB = sSC[mg * 16 + lr + 8];
        float* oA = out + (size_t)(b * LXX + x0 + mg * 16 + lr) * DD + w * 32;
        float* oB = oA + 8 * DD;
#pragma unroll
        for (int df = 0; df < 4; df++) {
            int c = df * 8 + tig * 2;
            *(float2*)(oA + c) = make_float2(O[mg * 4 + df][0] * iA,
                                             O[mg * 4 + df][1] * iA);
            *(float2*)(oB + c) = make_float2(O[mg * 4 + df][2] * iB,
                                             O[mg * 4 + df][3] * iB);
        }
    }
}

// ---------------------------------------------------------------------------
extern "C" void kernel_launch(void* const* d_in, const int* in_sizes, int n_in,
                              void* d_out, int out_size)
{
    const float* x    = (const float*)d_in[0];
    const float* y    = (const float*)d_in[1];
    const int* mask   = (const int*)d_in[2];
    const float* W    = (const float*)d_in[3];
    const float* bias = (const float*)d_in[4];
    float* out        = (float*)d_out;

    split_W<<<(DD * DD) / (256 * 4), 256>>>(W);
    split_x<<<(BB * LXX * DD) / (256 * 4), 256>>>(x);
    split_y<<<(BB * LYY * DD) / (256 * 4), 256>>>(y);

    cudaFuncSetAttribute(proj_mma_kernel,
                         cudaFuncAttributeMaxDynamicSharedMemorySize, QTOT);
    proj_mma_kernel<<<dim3((BB * (LXX + LYY)) / 128, 2), 256, QTOT>>>(bias);

    cudaFuncSetAttribute(attn_mma_kernel,
                         cudaFuncAttributeMaxDynamicSharedMemorySize, SMTOT);
    attn_mma_kernel<<<dim3(LXX / 128, BB), 256, SMTOT>>>(mask, out);
}

// round 12
// speedup vs baseline: 2.5542x; 1.0646x over previous
#include <cuda_runtime.h>
#include <cuda_bf16.h>
#include <cstdint>

#define BB 8
#define LXX 2048
#define LYY 2048
#define DD 256

// ---------------- global scratch (no cudaMalloc allowed) ----------------
__device__ __nv_bfloat16 g_x_h[BB * LXX * DD];    // raw x, bf16 hi/lo
__device__ __nv_bfloat16 g_x_l[BB * LXX * DD];
__device__ __nv_bfloat16 g_xp_h[BB * LXX * DD];
__device__ __nv_bfloat16 g_xp_l[BB * LXX * DD];
__device__ __nv_bfloat16 g_yp_h[BB * LYY * DD];
__device__ __nv_bfloat16 g_yp_l[BB * LYY * DD];
__device__ __nv_bfloat16 g_yv_h[BB * LYY * DD];   // raw y, bf16 hi/lo
__device__ __nv_bfloat16 g_yv_l[BB * LYY * DD];
__device__ __nv_bfloat16 g_W_h[DD * DD];
__device__ __nv_bfloat16 g_W_l[DD * DD];

// ---------------- helpers (portable PTX only: sm_80-era) ----------------
__device__ __forceinline__ uint32_t smem_u32(const void* p) {
    uint32_t a;
    asm("{ .reg .u64 t; cvta.to.shared.u64 t, %1; cvt.u32.u64 %0, t; }" : "=r"(a) : "l"(p));
    return a;
}
__device__ __forceinline__ void cpa16(uint32_t s, const void* g) {
    asm volatile("cp.async.cg.shared.global [%0], [%1], 16;" :: "r"(s), "l"(g));
}
__device__ __forceinline__ void cpa4(uint32_t s, const void* g) {
    asm volatile("cp.async.ca.shared.global [%0], [%1], 4;" :: "r"(s), "l"(g));
}
#define CP_COMMIT() asm volatile("cp.async.commit_group;" ::: "memory")
#define CP_WAIT0()  asm volatile("cp.async.wait_group 0;" ::: "memory")
#define CP_WAIT1()  asm volatile("cp.async.wait_group 1;" ::: "memory")

__device__ __forceinline__ void ldsm4(uint32_t r[4], uint32_t a) {
    asm volatile("ldmatrix.sync.aligned.m8n8.x4.shared.b16 {%0,%1,%2,%3}, [%4];"
                 : "=r"(r[0]), "=r"(r[1]), "=r"(r[2]), "=r"(r[3]) : "r"(a));
}
__device__ __forceinline__ void ldsm4t(uint32_t r[4], uint32_t a) {
    asm volatile("ldmatrix.sync.aligned.m8n8.x4.trans.shared.b16 {%0,%1,%2,%3}, [%4];"
                 : "=r"(r[0]), "=r"(r[1]), "=r"(r[2]), "=r"(r[3]) : "r"(a));
}
__device__ __forceinline__ void mma16816(float c[4], const uint32_t a[4],
                                         uint32_t b0, uint32_t b1) {
    asm volatile(
        "mma.sync.aligned.m16n8k16.row.col.f32.bf16.bf16.f32 "
        "{%0,%1,%2,%3}, {%4,%5,%6,%7}, {%8,%9}, {%0,%1,%2,%3};"
        : "+f"(c[0]), "+f"(c[1]), "+f"(c[2]), "+f"(c[3])
        : "r"(a[0]), "r"(a[1]), "r"(a[2]), "r"(a[3]), "r"(b0), "r"(b1));
}
__device__ __forceinline__ uint32_t cvt2bf(float lo, float hi) {
    uint32_t r;
    asm("cvt.rn.bf16x2.f32 %0, %1, %2;" : "=r"(r) : "f"(hi), "f"(lo));
    return r;
}
__device__ __forceinline__ float exp2p(float t) {
    t = fmaxf(t, -126.0f);
    float n = rintf(t);
    float f = t - n;
    float p = fmaf(1.5403530e-4f, f, 1.3333558e-3f);
    p = fmaf(p, f, 9.6181290e-3f);
    p = fmaf(p, f, 5.5504109e-2f);
    p = fmaf(p, f, 2.4022651e-1f);
    p = fmaf(p, f, 6.9314718e-1f);
    p = fmaf(p, f, 1.0f);
    return p * __int_as_float(((int)n + 127) << 23);
}
#define L2E 1.4426950408889634f

// ---------------------------------------------------------------------------
// Elementwise bf16 hi/lo splitters
// ---------------------------------------------------------------------------
__global__ __launch_bounds__(256)
void split_W(const float* __restrict__ W)
{
    size_t i = ((size_t)blockIdx.x * 256 + threadIdx.x) * 4;
    float4 v = *(const float4*)(W + i);
    float vv[4] = {v.x, v.y, v.z, v.w};
    __nv_bfloat16 h[4], l[4];
#pragma unroll
    for (int k = 0; k < 4; k++) {
        h[k] = __float2bfloat16_rn(vv[k]);
        l[k] = __float2bfloat16_rn(vv[k] - __bfloat162float(h[k]));
    }
    *(uint2*)&g_W_h[i] = *(uint2*)h;
    *(uint2*)&g_W_l[i] = *(uint2*)l;
}
// blocks [0, N/1024) -> x, rest -> y
__global__ __launch_bounds__(256)
void split_xy(const float* __restrict__ x, const float* __restrict__ y)
{
    const int half = (BB * LXX * DD) / (256 * 4);
    const float* src;
    __nv_bfloat16 *dh, *dl;
    size_t i;
    if (blockIdx.x < half) {
        src = x; dh = g_x_h; dl = g_x_l;
        i = ((size_t)blockIdx.x * 256 + threadIdx.x) * 4;
    } else {
        src = y; dh = g_yv_h; dl = g_yv_l;
        i = ((size_t)(blockIdx.x - half) * 256 + threadIdx.x) * 4;
    }
    float4 v = *(const float4*)(src + i);
    float vv[4] = {v.x, v.y, v.z, v.w};
    __nv_bfloat16 h[4], l[4];
#pragma unroll
    for (int k = 0; k < 4; k++) {
        h[k] = __float2bfloat16_rn(vv[k]);
        l[k] = __float2bfloat16_rn(vv[k] - __bfloat162float(h[k]));
    }
    *(uint2*)&dh[i] = *(uint2*)h;
    *(uint2*)&dl[i] = *(uint2*)l;
}

// ---------------------------------------------------------------------------
// Tensor-core projection: C = relu(A @ W^T + b) -> bf16 h/l splits.
// CTA = 128 rows x 128 cols. W-half RESIDENT in smem; A streamed in k32
// double-buffered stages. 3-pass hh+hl+lh. Register double-buffered W frags.
// ---------------------------------------------------------------------------
#define QW_H 0
#define QW_L 67584          // 128 x 528
#define QA_H 135168         // 2 stages x 10240 (128 rows x 80B)
#define QA_L 155648
#define QTOT 176128
#define QASTR 80

__global__ __launch_bounds__(256, 1)
void proj_mma_kernel(const float* __restrict__ bias)
{
    extern __shared__ char smc[];
    const uint32_t sa = smem_u32(smc);
    const int tid  = threadIdx.x;
    const int w    = tid >> 5;
    const int lane = tid & 31;
    const int lr   = lane >> 2;
    const int tig  = lane & 3;
    const int rw   = w * 16;
    const int wcol0 = blockIdx.y * 128;
    const int row0  = blockIdx.x * 128;
    const bool isx  = row0 < BB * LXX;
    const int arow0 = isx ? row0 : row0 - BB * LXX;

    const __nv_bfloat16* __restrict__ Ah = isx ? g_x_h : g_yv_h;
    const __nv_bfloat16* __restrict__ Al = isx ? g_x_l : g_yv_l;
    __nv_bfloat16* __restrict__ Ch = isx ? g_xp_h : g_yp_h;
    __nv_bfloat16* __restrict__ Cl = isx ? g_xp_l : g_yp_l;

    // ---- resident W half (h+l) + first A stage ----
    {
        int r = tid >> 1, hb = (tid & 1) * 16;
        const __nv_bfloat16* wh = g_W_h + (size_t)(wcol0 + r) * DD + hb * 8;
        const __nv_bfloat16* wl = g_W_l + (size_t)(wcol0 + r) * DD + hb * 8;
        uint32_t dh = sa + QW_H + r * 528 + hb * 16;
        uint32_t dl = sa + QW_L + r * 528 + hb * 16;
#pragma unroll
        for (int i = 0; i < 16; i++) {
            cpa16(dh + i * 16, wh + i * 8);
            cpa16(dl + i * 16, wl + i * 8);
        }
    }
    auto prefA = [&](int s, int kc) {
        int r = tid >> 1, hb = tid & 1;
        const __nv_bfloat16* ph = Ah + (size_t)(arow0 + r) * DD + kc * 32 + hb * 16;
        const __nv_bfloat16* pl = Al + (size_t)(arow0 + r) * DD + kc * 32 + hb * 16;
        uint32_t dh = sa + QA_H + s * 10240 + r * QASTR + hb * 32;
        uint32_t dl = sa + QA_L + s * 10240 + r * QASTR + hb * 32;
        cpa16(dh, ph); cpa16(dh + 16, ph + 8);
        cpa16(dl, pl); cpa16(dl + 16, pl + 8);
    };
    prefA(0, 0);
    CP_COMMIT();

    float O[16][4];
#pragma unroll
    for (int i = 0; i < 16; i++) { O[i][0] = O[i][1] = O[i][2] = O[i][3] = 0.f; }

    const uint32_t aA  = sa + QA_H + (rw + (lane & 7) + ((lane >> 3) & 1) * 8) * QASTR
                       + (lane >> 4) * 16;
    const uint32_t aAl = aA + (uint32_t)(QA_L - QA_H);
    const uint32_t aW  = sa + QW_H + ((lane & 7) + ((lane < 16) ? 0 : 8)) * 528
                       + ((lane >> 3) & 1) * 16;
    const uint32_t aWl = aW + (uint32_t)(QW_L - QW_H);

#pragma unroll 1
    for (int kc = 0; kc < 8; kc++) {
        const int s = kc & 1;
        if (kc < 7) { prefA(s ^ 1, kc + 1); CP_COMMIT(); CP_WAIT1(); }
        else        { CP_WAIT0(); }
        __syncthreads();

        const uint32_t sOff = (uint32_t)(s * 10240);
#pragma unroll
        for (int kk = 0; kk < 2; kk++) {
            uint32_t ah[4], al[4];
            ldsm4(ah, aA  + sOff + kk * 32);
            ldsm4(al, aAl + sOff + kk * 32);
            const uint32_t kOff = (uint32_t)(kc * 64 + kk * 32);
            // register double-buffered W frags across g
            uint32_t wb[2][8];
            ldsm4(&wb[0][0], aW  + kOff);
            ldsm4(&wb[0][4], aWl + kOff);
#pragma unroll
            for (int g = 0; g < 8; g++) {
                const int cur = g & 1, nxt = cur ^ 1;
                if (g < 7) {
                    ldsm4(&wb[nxt][0], aW  + (g + 1) * (16 * 528) + kOff);
                    ldsm4(&wb[nxt][4], aWl + (g + 1) * (16 * 528) + kOff);
                }
                const uint32_t* bh = &wb[cur][0];
                const uint32_t* bl = &wb[cur][4];
                mma16816(O[2 * g],     ah, bh[0], bh[1]);
                mma16816(O[2 * g],     ah, bl[0], bl[1]);
                mma16816(O[2 * g],     al, bh[0], bh[1]);
                mma16816(O[2 * g + 1], ah, bh[2], bh[3]);
                mma16816(O[2 * g + 1], ah, bl[2], bl[3]);
                mma16816(O[2 * g + 1], al, bh[2], bh[3]);
            }
        }
        __syncthreads();
    }

    // ---- epilogue: bias + relu + h/l split + store ----
    const int r0g = arow0 + rw + lr;
#pragma unroll
    for (int f = 0; f < 16; f++) {
        int c = wcol0 + f * 8 + tig * 2;
        float b0 = __ldg(bias + c), b1 = __ldg(bias + c + 1);
        {
            float v0 = fmaxf(O[f][0] + b0, 0.f), v1 = fmaxf(O[f][1] + b1, 0.f);
            uint32_t h = cvt2bf(v0, v1);
            float q0 = v0 - __uint_as_float(h << 16);
            float q1 = v1 - __uint_as_float(h & 0xffff0000u);
            uint32_t l = cvt2bf(q0, q1);
            size_t o = (size_t)r0g * DD + c;
            *(uint32_t*)&Ch[o] = h;
            *(uint32_t*)&Cl[o] = l;
        }
        {
            float v0 = fmaxf(O[f][2] + b0, 0.f), v1 = fmaxf(O[f][3] + b1, 0.f);
            uint32_t h = cvt2bf(v0, v1);
            float q0 = v0 - __uint_as_float(h << 16);
            float q1 = v1 - __uint_as_float(h & 0xffff0000u);
            uint32_t l = cvt2bf(q0, q1);
            size_t o = (size_t)(r0g + 8) * DD + c;
            *(uint32_t*)&Ch[o] = h;
            *(uint32_t*)&Cl[o] = l;
        }
    }
}

// ---------------------------------------------------------------------------
// Fused mma.sync attention: 256 threads, XTILE 128, JTILE 32.
// S phase: warp = 16 rows x 32 cols, 3-pass hh+hl+lh, register double-buffered
// fragments (ldsm kk+1 overlaps mma kk). PV: d-split + P-frag prefetch.
// ---------------------------------------------------------------------------
#define SXSTR 528
#define SXH 0
#define SXL (SXH + 128 * SXSTR)
#define SBH (SXL + 128 * SXSTR)
#define SBL (SBH + 32 * SXSTR)
#define SVH (SBL + 32 * SXSTR)
#define SVL (SVH + 32 * SXSTR)
#define SPH (SVL + 32 * SXSTR)
#define SSC (SPH + 128 * 80)
#define SMK (SSC + 512)
#define SMTOT (SMK + 128)
#define NT (LYY / 32)

__global__ __launch_bounds__(256, 1)
void attn_mma_kernel(const int* __restrict__ mask, float* __restrict__ out)
{
    extern __shared__ char smc[];
    const uint32_t sa = smem_u32(smc);
    const int tid  = threadIdx.x;
    const int w    = tid >> 5;
    const int lane = tid & 31;
    const int lr   = lane >> 2;
    const int tig  = lane & 3;
    const int b    = blockIdx.y;
    const int x0   = blockIdx.x * 128;
    const int rw   = w * 16;

    const int* mB = mask + (size_t)b * LYY;
    const size_t gyB = (size_t)(b * LYY) * DD;
    const int pr = tid >> 3, pcb = tid & 7;

    auto issueYp = [&](int t) {
        size_t gro = gyB + (size_t)(t * 32 + pr) * DD;
        uint32_t o = sa + (uint32_t)(pr * SXSTR);
#pragma unroll
        for (int i = 0; i < 4; i++) {
            int c = pcb + 8 * i;
            cpa16(o + SBH + c * 16, g_yp_h + gro + c * 8);
            cpa16(o + SBL + c * 16, g_yp_l + gro + c * 8);
        }
        if (tid < 32) cpa4(sa + SMK + tid * 4, mB + t * 32 + tid);
    };
    auto issueYv = [&](int t) {
        size_t gro = gyB + (size_t)(t * 32 + pr) * DD;
        uint32_t o = sa + (uint32_t)(pr * SXSTR);
#pragma unroll
        for (int i = 0; i < 4; i++) {
            int c = pcb + 8 * i;
            cpa16(o + SVH + c * 16, g_yv_h + gro + c * 8);
            cpa16(o + SVL + c * 16, g_yv_l + gro + c * 8);
        }
    };

    {
        int r = tid >> 1;
        const __nv_bfloat16* srch = g_xp_h + (size_t)(b * LXX + x0 + r) * DD;
        const __nv_bfloat16* srcl = g_xp_l + (size_t)(b * LXX + x0 + r) * DD;
        uint32_t dh = sa + SXH + r * SXSTR;
        uint32_t dl = sa + SXL + r * SXSTR;
#pragma unroll
        for (int i = 0; i < 16; i++) {
            int c = (tid & 1) + 2 * i;
            cpa16(dh + c * 16, srch + c * 8);
            cpa16(dl + c * 16, srcl + c * 8);
        }
    }
    CP_COMMIT();
    issueYp(0);
    CP_COMMIT();
    issueYv(0);
    CP_COMMIT();

    const int* smk = (const int*)(smc + SMK);
    float* sSC = (float*)(smc + SSC);

    float O[32][4];
#pragma unroll
    for (int i = 0; i < 32; i++) { O[i][0] = O[i][1] = O[i][2] = O[i][3] = 0.f; }
    float m0 = -1e30f, m1 = -1e30f, l0 = 0.f, l1 = 0.f;

    const uint32_t aA  = sa + SXH + (rw + (lane & 7) + ((lane >> 3) & 1) * 8) * SXSTR
                       + (lane >> 4) * 16;
    const uint32_t aAl = aA + (uint32_t)(SXL - SXH);
    const uint32_t aB  = sa + SBH + ((lane & 7) + ((lane < 16) ? 0 : 8)) * SXSTR
                       + ((lane >> 3) & 1) * 16;
    const uint32_t aBl = aB + (uint32_t)(SBL - SBH);
    const uint32_t aP  = sa + SPH + ((lane & 7) + ((lane >> 3) & 1) * 8) * 80
                       + (lane >> 4) * 16;
    const uint32_t aVd = sa + SVH + ((lane & 7) + ((lane >> 3) & 1) * 8) * SXSTR
                       + w * 64 + ((lane < 16) ? 0 : 16);
    const uint32_t aVdl = aVd + (uint32_t)(SVL - SVH);

    const int r0 = rw + lr, r1 = rw + lr + 8;

#pragma unroll 1
    for (int t = 0; t < NT; t++) {
        CP_WAIT1();
        __syncthreads();

        float sf[4][4];
#pragma unroll
        for (int nt = 0; nt < 4; nt++)
#pragma unroll
            for (int i = 0; i < 4; i++) sf[nt][i] = 0.f;

        // ---- S: register double-buffered frags ----
        uint32_t fa[2][8], fb[2][16];
        ldsm4(&fa[0][0], aA);
        ldsm4(&fa[0][4], aAl);
        ldsm4(&fb[0][0], aB);
        ldsm4(&fb[0][4], aBl);
        ldsm4(&fb[0][8], aB + 16 * SXSTR);
        ldsm4(&fb[0][12], aBl + 16 * SXSTR);
#pragma unroll
        for (int kk = 0; kk < 16; kk++) {
            const int cur = kk & 1, nxt = cur ^ 1;
            if (kk < 15) {
                const uint32_t ko = (uint32_t)((kk + 1) * 32);
                ldsm4(&fa[nxt][0], aA  + ko);
                ldsm4(&fa[nxt][4], aAl + ko);
                ldsm4(&fb[nxt][0], aB  + ko);
                ldsm4(&fb[nxt][4], aBl + ko);
                ldsm4(&fb[nxt][8], aB  + 16 * SXSTR + ko);
                ldsm4(&fb[nxt][12], aBl + 16 * SXSTR + ko);
            }
            const uint32_t* ah = &fa[cur][0];
            const uint32_t* al = &fa[cur][4];
            const uint32_t* bh = &fb[cur][0];
            const uint32_t* bl = &fb[cur][4];
            const uint32_t* ch = &fb[cur][8];
            const uint32_t* cl = &fb[cur][12];
            mma16816(sf[0], ah, bh[0], bh[1]);
            mma16816(sf[0], ah, bl[0], bl[1]);
            mma16816(sf[0], al, bh[0], bh[1]);
            mma16816(sf[1], ah, bh[2], bh[3]);
            mma16816(sf[1], ah, bl[2], bl[3]);
            mma16816(sf[1], al, bh[2], bh[3]);
            mma16816(sf[2], ah, ch[0], ch[1]);
            mma16816(sf[2], ah, cl[0], cl[1]);
            mma16816(sf[2], al, ch[0], ch[1]);
            mma16816(sf[3], ah, ch[2], ch[3]);
            mma16816(sf[3], ah, cl[2], cl[3]);
            mma16816(sf[3], al, ch[2], ch[3]);
        }

        float mx0 = -1e30f, mx1 = -1e30f;
#pragma unroll
        for (int nt = 0; nt < 4; nt++) {
            int j = 8 * nt + 2 * tig;
            if (smk[j])     { sf[nt][0] = -1e30f; sf[nt][2] = -1e30f; }
            if (smk[j + 1]) { sf[nt][1] = -1e30f; sf[nt][3] = -1e30f; }
            mx0 = fmaxf(mx0, fmaxf(sf[nt][0], sf[nt][1]));
            mx1 = fmaxf(mx1, fmaxf(sf[nt][2], sf[nt][3]));
        }
        mx0 = fmaxf(mx0, __shfl_xor_sync(0xffffffffu, mx0, 1));
        mx0 = fmaxf(mx0, __shfl_xor_sync(0xffffffffu, mx0, 2));
        mx1 = fmaxf(mx1, __shfl_xor_sync(0xffffffffu, mx1, 1));
        mx1 = fmaxf(mx1, __shfl_xor_sync(0xffffffffu, mx1, 2));

        float mn0 = fmaxf(m0, mx0), mn1 = fmaxf(m1, mx1);
        float sc0 = exp2p((m0 - mn0) * L2E);
        float sc1 = exp2p((m1 - mn1) * L2E);
        m0 = mn0; m1 = mn1;

        uint32_t ph[8];
        float rs0 = 0.f, rs1 = 0.f;
#pragma unroll
        for (int nt = 0; nt < 4; nt++) {
            float p00 = exp2p((sf[nt][0] - mn0) * L2E);
            float p01 = exp2p((sf[nt][1] - mn0) * L2E);
            float p10 = exp2p((sf[nt][2] - mn1) * L2E);
            float p11 = exp2p((sf[nt][3] - mn1) * L2E);
            uint32_t h0 = cvt2bf(p00, p01);
            uint32_t h1 = cvt2bf(p10, p11);
            ph[nt * 2]     = h0;
            ph[nt * 2 + 1] = h1;
            rs0 += __uint_as_float(h0 << 16) + __uint_as_float(h0 & 0xffff0000u);
            rs1 += __uint_as_float(h1 << 16) + __uint_as_float(h1 & 0xffff0000u);
        }
        rs0 += __shfl_xor_sync(0xffffffffu, rs0, 1);
        rs0 += __shfl_xor_sync(0xffffffffu, rs0, 2);
        rs1 += __shfl_xor_sync(0xffffffffu, rs1, 1);
        rs1 += __shfl_xor_sync(0xffffffffu, rs1, 2);
        l0 = l0 * sc0 + rs0;
        l1 = l1 * sc1 + rs1;

#pragma unroll
        for (int nt = 0; nt < 4; nt++) {
            *(uint32_t*)(smc + SPH + r0 * 80 + 16 * nt + 4 * tig) = ph[nt * 2];
            *(uint32_t*)(smc + SPH + r1 * 80 + 16 * nt + 4 * tig) = ph[nt * 2 + 1];
        }
        if (tig == 0) { sSC[r0] = sc0; sSC[r1] = sc1; }
        __syncthreads();

        if (t < NT - 1) issueYp(t + 1);
        CP_COMMIT();

#pragma unroll
        for (int mg = 0; mg < 8; mg++) {
            float sA = sSC[mg * 16 + lr];
            float sB = sSC[mg * 16 + lr + 8];
#pragma unroll
            for (int df = 0; df < 4; df++) {
                O[mg * 4 + df][0] *= sA; O[mg * 4 + df][1] *= sA;
                O[mg * 4 + df][2] *= sB; O[mg * 4 + df][3] *= sB;
            }
        }

        if (t < NT - 1) { CP_WAIT1(); } else { CP_WAIT0(); }
        __syncthreads();

        // ---- PV: O[all rows, d32 slice] += Ph @ (Vh + Vl), P-frag prefetch ----
#pragma unroll
        for (int k = 0; k < 2; k++) {
            uint32_t vh0[4], vl0[4], vh1[4], vl1[4];
            ldsm4t(vh0, aVd  + k * 16 * SXSTR);
            ldsm4t(vh1, aVd  + k * 16 * SXSTR + 32);
            ldsm4t(vl0, aVdl + k * 16 * SXSTR);
            ldsm4t(vl1, aVdl + k * 16 * SXSTR + 32);
            uint32_t pa[2][4];
            ldsm4(pa[0], aP + k * 32);
#pragma unroll
            for (int mg = 0; mg < 8; mg++) {
                const int cur = mg & 1, nxt = cur ^ 1;
                if (mg < 7) ldsm4(pa[nxt], aP + (mg + 1) * 1280 + k * 32);
                const uint32_t* pA = pa[cur];
                mma16816(O[mg * 4 + 0], pA, vh0[0], vh0[1]);
                mma16816(O[mg * 4 + 0], pA, vl0[0], vl0[1]);
                mma16816(O[mg * 4 + 1], pA, vh0[2], vh0[3]);
                mma16816(O[mg * 4 + 1], pA, vl0[2], vl0[3]);
                mma16816(O[mg * 4 + 2], pA, vh1[0], vh1[1]);
                mma16816(O[mg * 4 + 2], pA, vl1[0], vl1[1]);
                mma16816(O[mg * 4 + 3], pA, vh1[2], vh1[3]);
                mma16816(O[mg * 4 + 3], pA, vl1[2], vl1[3]);
            }
        }
        __syncthreads();

        if (t < NT - 1) issueYv(t + 1);
        CP_COMMIT();
    }

    if (tig == 0) { sSC[r0] = 1.0f / l0; sSC[r1] = 1.0f / l1; }
    __syncthreads();
#pragma unroll
    for (int mg = 0; mg < 8; mg++) {
        float iA = sSC[mg * 16 + lr];
        float iB = sSC[mg * 16 + lr + 8];
        float* oA = out + (size_t)(b * LXX + x0 + mg * 16 + lr) * DD + w * 32;
        float* oB = oA + 8 * DD;
#pragma unroll
        for (int df = 0; df < 4; df++) {
            int c = df * 8 + tig * 2;
            *(float2*)(oA + c) = make_float2(O[mg * 4 + df][0] * iA,
                                             O[mg * 4 + df][1] * iA);
            *(float2*)(oB + c) = make_float2(O[mg * 4 + df][2] * iB,
                                             O[mg * 4 + df][3] * iB);
        }
    }
}

// ---------------------------------------------------------------------------
extern "C" void kernel_launch(void* const* d_in, const int* in_sizes, int n_in,
                              void* d_out, int out_size)
{
    const float* x    = (const float*)d_in[0];
    const float* y    = (const float*)d_in[1];
    const int* mask   = (const int*)d_in[2];
    const float* W    = (const float*)d_in[3];
    const float* bias = (const float*)d_in[4];
    float* out        = (float*)d_out;

    split_W<<<(DD * DD) / (256 * 4), 256>>>(W);
    split_xy<<<(2 * BB * LXX * DD) / (256 * 4), 256>>>(x, y);

    cudaFuncSetAttribute(proj_mma_kernel,
                         cudaFuncAttributeMaxDynamicSharedMemorySize, QTOT);
    proj_mma_kernel<<<dim3((BB * (LXX + LYY)) / 128, 2), 256, QTOT>>>(bias);

    cudaFuncSetAttribute(attn_mma_kernel,
                         cudaFuncAttributeMaxDynamicSharedMemorySize, SMTOT);
    attn_mma_kernel<<<dim3(LXX / 128, BB), 256, SMTOT>>>(mask, out);
}

// round 13
// speedup vs baseline: 2.7690x; 1.0841x over previous
#include <cuda_runtime.h>
#include <cuda_bf16.h>
#include <cstdint>

#define BB 8
#define LXX 2048
#define LYY 2048
#define DD 256

// ---------------- global scratch (no cudaMalloc allowed) ----------------
__device__ __nv_bfloat16 g_x_h[BB * LXX * DD];    // raw x, bf16 hi/lo
__device__ __nv_bfloat16 g_x_l[BB * LXX * DD];
__device__ __nv_bfloat16 g_xp_h[BB * LXX * DD];
__device__ __nv_bfloat16 g_xp_l[BB * LXX * DD];
__device__ __nv_bfloat16 g_yp_h[BB * LYY * DD];
__device__ __nv_bfloat16 g_yp_l[BB * LYY * DD];
__device__ __nv_bfloat16 g_yv_h[BB * LYY * DD];   // raw y, bf16 hi/lo
__device__ __nv_bfloat16 g_yv_l[BB * LYY * DD];
__device__ __nv_bfloat16 g_W_h[DD * DD];
__device__ __nv_bfloat16 g_W_l[DD * DD];

// ---------------- helpers (portable PTX only: sm_80-era) ----------------
__device__ __forceinline__ uint32_t smem_u32(const void* p) {
    uint32_t a;
    asm("{ .reg .u64 t; cvta.to.shared.u64 t, %1; cvt.u32.u64 %0, t; }" : "=r"(a) : "l"(p));
    return a;
}
__device__ __forceinline__ void cpa16(uint32_t s, const void* g) {
    asm volatile("cp.async.cg.shared.global [%0], [%1], 16;" :: "r"(s), "l"(g));
}
__device__ __forceinline__ void cpa4(uint32_t s, const void* g) {
    asm volatile("cp.async.ca.shared.global [%0], [%1], 4;" :: "r"(s), "l"(g));
}
#define CP_COMMIT() asm volatile("cp.async.commit_group;" ::: "memory")
#define CP_WAIT0()  asm volatile("cp.async.wait_group 0;" ::: "memory")
#define CP_WAIT1()  asm volatile("cp.async.wait_group 1;" ::: "memory")

__device__ __forceinline__ void ldsm4(uint32_t r[4], uint32_t a) {
    asm volatile("ldmatrix.sync.aligned.m8n8.x4.shared.b16 {%0,%1,%2,%3}, [%4];"
                 : "=r"(r[0]), "=r"(r[1]), "=r"(r[2]), "=r"(r[3]) : "r"(a));
}
__device__ __forceinline__ void ldsm4t(uint32_t r[4], uint32_t a) {
    asm volatile("ldmatrix.sync.aligned.m8n8.x4.trans.shared.b16 {%0,%1,%2,%3}, [%4];"
                 : "=r"(r[0]), "=r"(r[1]), "=r"(r[2]), "=r"(r[3]) : "r"(a));
}
__device__ __forceinline__ void mma16816(float c[4], const uint32_t a[4],
                                         uint32_t b0, uint32_t b1) {
    asm volatile(
        "mma.sync.aligned.m16n8k16.row.col.f32.bf16.bf16.f32 "
        "{%0,%1,%2,%3}, {%4,%5,%6,%7}, {%8,%9}, {%0,%1,%2,%3};"
        : "+f"(c[0]), "+f"(c[1]), "+f"(c[2]), "+f"(c[3])
        : "r"(a[0]), "r"(a[1]), "r"(a[2]), "r"(a[3]), "r"(b0), "r"(b1));
}
__device__ __forceinline__ uint32_t cvt2bf(float lo, float hi) {
    uint32_t r;
    asm("cvt.rn.bf16x2.f32 %0, %1, %2;" : "=r"(r) : "f"(hi), "f"(lo));
    return r;
}
__device__ __forceinline__ float exp2p(float t) {
    t = fmaxf(t, -126.0f);
    float n = rintf(t);
    float f = t - n;
    float p = fmaf(1.5403530e-4f, f, 1.3333558e-3f);
    p = fmaf(p, f, 9.6181290e-3f);
    p = fmaf(p, f, 5.5504109e-2f);
    p = fmaf(p, f, 2.4022651e-1f);
    p = fmaf(p, f, 6.9314718e-1f);
    p = fmaf(p, f, 1.0f);
    return p * __int_as_float(((int)n + 127) << 23);
}
#define L2E 1.4426950408889634f

// ---------------------------------------------------------------------------
// Elementwise bf16 hi/lo splitters
// ---------------------------------------------------------------------------
__global__ __launch_bounds__(256)
void split_W(const float* __restrict__ W)
{
    size_t i = ((size_t)blockIdx.x * 256 + threadIdx.x) * 4;
    float4 v = *(const float4*)(W + i);
    float vv[4] = {v.x, v.y, v.z, v.w};
    __nv_bfloat16 h[4], l[4];
#pragma unroll
    for (int k = 0; k < 4; k++) {
        h[k] = __float2bfloat16_rn(vv[k]);
        l[k] = __float2bfloat16_rn(vv[k] - __bfloat162float(h[k]));
    }
    *(uint2*)&g_W_h[i] = *(uint2*)h;
    *(uint2*)&g_W_l[i] = *(uint2*)l;
}
// blocks [0, N/1024) -> x, rest -> y
__global__ __launch_bounds__(256)
void split_xy(const float* __restrict__ x, const float* __restrict__ y)
{
    const int half = (BB * LXX * DD) / (256 * 4);
    const float* src;
    __nv_bfloat16 *dh, *dl;
    size_t i;
    if (blockIdx.x < half) {
        src = x; dh = g_x_h; dl = g_x_l;
        i = ((size_t)blockIdx.x * 256 + threadIdx.x) * 4;
    } else {
        src = y; dh = g_yv_h; dl = g_yv_l;
        i = ((size_t)(blockIdx.x - half) * 256 + threadIdx.x) * 4;
    }
    float4 v = *(const float4*)(src + i);
    float vv[4] = {v.x, v.y, v.z, v.w};
    __nv_bfloat16 h[4], l[4];
#pragma unroll
    for (int k = 0; k < 4; k++) {
        h[k] = __float2bfloat16_rn(vv[k]);
        l[k] = __float2bfloat16_rn(vv[k] - __bfloat162float(h[k]));
    }
    *(uint2*)&dh[i] = *(uint2*)h;
    *(uint2*)&dl[i] = *(uint2*)l;
}

// ---------------------------------------------------------------------------
// Tensor-core projection v2: C = relu(A @ W^T + b) -> bf16 h/l splits.
// CTA = 128 rows x 128 cols. BOTH A and W streamed per k32 chunk (W stays
// L2-hot), double-buffered stages => smem 80KB => 2 CTAs/SM (4 warps/SMSP).
// 3-pass hh+hl+lh. W frags register double-buffered across g.
// ---------------------------------------------------------------------------
#define PJ_AH 0
#define PJ_AL 10240
#define PJ_WH 20480
#define PJ_WL 30720
#define PJ_STG 40960
#define PJ_TOT (2 * PJ_STG)

__global__ __launch_bounds__(256, 2)
void proj_mma_kernel(const float* __restrict__ bias)
{
    extern __shared__ char smc[];
    const uint32_t sa = smem_u32(smc);
    const int tid  = threadIdx.x;
    const int w    = tid >> 5;
    const int lane = tid & 31;
    const int lr   = lane >> 2;
    const int tig  = lane & 3;
    const int rw   = w * 16;
    const int wcol0 = blockIdx.y * 128;
    const int row0  = blockIdx.x * 128;
    const bool isx  = row0 < BB * LXX;
    const int arow0 = isx ? row0 : row0 - BB * LXX;

    const __nv_bfloat16* __restrict__ Ah = isx ? g_x_h : g_yv_h;
    const __nv_bfloat16* __restrict__ Al = isx ? g_x_l : g_yv_l;
    __nv_bfloat16* __restrict__ Ch = isx ? g_xp_h : g_yp_h;
    __nv_bfloat16* __restrict__ Cl = isx ? g_xp_l : g_yp_l;

    const int pre_r = tid >> 1, pre_hb = tid & 1;   // 32B per thread per tensor

    auto pref = [&](int s, int kc) {
        const uint32_t st = sa + (uint32_t)(s * PJ_STG + pre_r * 80 + pre_hb * 32);
        const size_t ao = (size_t)(arow0 + pre_r) * DD + kc * 32 + pre_hb * 16;
        const size_t wo = (size_t)(wcol0 + pre_r) * DD + kc * 32 + pre_hb * 16;
        cpa16(st + PJ_AH,      Ah + ao);  cpa16(st + PJ_AH + 16,  Ah + ao + 8);
        cpa16(st + PJ_AL,      Al + ao);  cpa16(st + PJ_AL + 16,  Al + ao + 8);
        cpa16(st + PJ_WH,      g_W_h + wo); cpa16(st + PJ_WH + 16, g_W_h + wo + 8);
        cpa16(st + PJ_WL,      g_W_l + wo); cpa16(st + PJ_WL + 16, g_W_l + wo + 8);
    };
    pref(0, 0);
    CP_COMMIT();

    float O[16][4];
#pragma unroll
    for (int i = 0; i < 16; i++) { O[i][0] = O[i][1] = O[i][2] = O[i][3] = 0.f; }

    const uint32_t aAo = (uint32_t)(PJ_AH + (rw + (lane & 7) + ((lane >> 3) & 1) * 8) * 80
                        + (lane >> 4) * 16);
    const uint32_t aWo = (uint32_t)(PJ_WH + ((lane & 7) + ((lane < 16) ? 0 : 8)) * 80
                        + ((lane >> 3) & 1) * 16);

#pragma unroll 1
    for (int kc = 0; kc < 8; kc++) {
        const int s = kc & 1;
        if (kc < 7) { pref(s ^ 1, kc + 1); CP_COMMIT(); CP_WAIT1(); }
        else        { CP_WAIT0(); }
        __syncthreads();

        const uint32_t stb = sa + (uint32_t)(s * PJ_STG);
        const uint32_t aA  = stb + aAo;
        const uint32_t aAl = aA + (PJ_AL - PJ_AH);
        const uint32_t aW  = stb + aWo;
        const uint32_t aWl = aW + (PJ_WL - PJ_WH);
#pragma unroll
        for (int kk = 0; kk < 2; kk++) {
            uint32_t ah[4], al[4];
            ldsm4(ah, aA  + kk * 32);
            ldsm4(al, aAl + kk * 32);
            // register double-buffered W frags across g
            uint32_t wb[2][8];
            ldsm4(&wb[0][0], aW  + kk * 32);
            ldsm4(&wb[0][4], aWl + kk * 32);
#pragma unroll
            for (int g = 0; g < 8; g++) {
                const int cur = g & 1, nxt = cur ^ 1;
                if (g < 7) {
                    ldsm4(&wb[nxt][0], aW  + (g + 1) * 1280 + kk * 32);
                    ldsm4(&wb[nxt][4], aWl + (g + 1) * 1280 + kk * 32);
                }
                const uint32_t* bh = &wb[cur][0];
                const uint32_t* bl = &wb[cur][4];
                mma16816(O[2 * g],     ah, bh[0], bh[1]);
                mma16816(O[2 * g],     ah, bl[0], bl[1]);
                mma16816(O[2 * g],     al, bh[0], bh[1]);
                mma16816(O[2 * g + 1], ah, bh[2], bh[3]);
                mma16816(O[2 * g + 1], ah, bl[2], bl[3]);
                mma16816(O[2 * g + 1], al, bh[2], bh[3]);
            }
        }
        __syncthreads();
    }

    // ---- epilogue: bias + relu + h/l split + store ----
    const int r0g = arow0 + rw + lr;
#pragma unroll
    for (int f = 0; f < 16; f++) {
        int c = wcol0 + f * 8 + tig * 2;
        float b0 = __ldg(bias + c), b1 = __ldg(bias + c + 1);
        {
            float v0 = fmaxf(O[f][0] + b0, 0.f), v1 = fmaxf(O[f][1] + b1, 0.f);
            uint32_t h = cvt2bf(v0, v1);
            float q0 = v0 - __uint_as_float(h << 16);
            float q1 = v1 - __uint_as_float(h & 0xffff0000u);
            uint32_t l = cvt2bf(q0, q1);
            size_t o = (size_t)r0g * DD + c;
            *(uint32_t*)&Ch[o] = h;
            *(uint32_t*)&Cl[o] = l;
        }
        {
            float v0 = fmaxf(O[f][2] + b0, 0.f), v1 = fmaxf(O[f][3] + b1, 0.f);
            uint32_t h = cvt2bf(v0, v1);
            float q0 = v0 - __uint_as_float(h << 16);
            float q1 = v1 - __uint_as_float(h & 0xffff0000u);
            uint32_t l = cvt2bf(q0, q1);
            size_t o = (size_t)(r0g + 8) * DD + c;
            *(uint32_t*)&Ch[o] = h;
            *(uint32_t*)&Cl[o] = l;
        }
    }
}

// ---------------------------------------------------------------------------
// Fused mma.sync attention: 256 threads, XTILE 128, JTILE 32.
// S phase: warp = 16 rows x 32 cols, 3-pass hh+hl+lh, register double-buffered
// fragments. PV: d-split + P-frag prefetch; O-rescale folded into PV (k==0).
// ---------------------------------------------------------------------------
#define SXSTR 528
#define SXH 0
#define SXL (SXH + 128 * SXSTR)
#define SBH (SXL + 128 * SXSTR)
#define SBL (SBH + 32 * SXSTR)
#define SVH (SBL + 32 * SXSTR)
#define SVL (SVH + 32 * SXSTR)
#define SPH (SVL + 32 * SXSTR)
#define SSC (SPH + 128 * 80)
#define SMK (SSC + 512)
#define SMTOT (SMK + 128)
#define NT (LYY / 32)

__global__ __launch_bounds__(256, 1)
void attn_mma_kernel(const int* __restrict__ mask, float* __restrict__ out)
{
    extern __shared__ char smc[];
    const uint32_t sa = smem_u32(smc);
    const int tid  = threadIdx.x;
    const int w    = tid >> 5;
    const int lane = tid & 31;
    const int lr   = lane >> 2;
    const int tig  = lane & 3;
    const int b    = blockIdx.y;
    const int x0   = blockIdx.x * 128;
    const int rw   = w * 16;

    const int* mB = mask + (size_t)b * LYY;
    const size_t gyB = (size_t)(b * LYY) * DD;
    const int pr = tid >> 3, pcb = tid & 7;

    auto issueYp = [&](int t) {
        size_t gro = gyB + (size_t)(t * 32 + pr) * DD;
        uint32_t o = sa + (uint32_t)(pr * SXSTR);
#pragma unroll
        for (int i = 0; i < 4; i++) {
            int c = pcb + 8 * i;
            cpa16(o + SBH + c * 16, g_yp_h + gro + c * 8);
            cpa16(o + SBL + c * 16, g_yp_l + gro + c * 8);
        }
        if (tid < 32) cpa4(sa + SMK + tid * 4, mB + t * 32 + tid);
    };
    auto issueYv = [&](int t) {
        size_t gro = gyB + (size_t)(t * 32 + pr) * DD;
        uint32_t o = sa + (uint32_t)(pr * SXSTR);
#pragma unroll
        for (int i = 0; i < 4; i++) {
            int c = pcb + 8 * i;
            cpa16(o + SVH + c * 16, g_yv_h + gro + c * 8);
            cpa16(o + SVL + c * 16, g_yv_l + gro + c * 8);
        }
    };

    {
        int r = tid >> 1;
        const __nv_bfloat16* srch = g_xp_h + (size_t)(b * LXX + x0 + r) * DD;
        const __nv_bfloat16* srcl = g_xp_l + (size_t)(b * LXX + x0 + r) * DD;
        uint32_t dh = sa + SXH + r * SXSTR;
        uint32_t dl = sa + SXL + r * SXSTR;
#pragma unroll
        for (int i = 0; i < 16; i++) {
            int c = (tid & 1) + 2 * i;
            cpa16(dh + c * 16, srch + c * 8);
            cpa16(dl + c * 16, srcl + c * 8);
        }
    }
    CP_COMMIT();
    issueYp(0);
    CP_COMMIT();
    issueYv(0);
    CP_COMMIT();

    const int* smk = (const int*)(smc + SMK);
    float* sSC = (float*)(smc + SSC);

    float O[32][4];
#pragma unroll
    for (int i = 0; i < 32; i++) { O[i][0] = O[i][1] = O[i][2] = O[i][3] = 0.f; }
    float m0 = -1e30f, m1 = -1e30f, l0 = 0.f, l1 = 0.f;

    const uint32_t aA  = sa + SXH + (rw + (lane & 7) + ((lane >> 3) & 1) * 8) * SXSTR
                       + (lane >> 4) * 16;
    const uint32_t aAl = aA + (uint32_t)(SXL - SXH);
    const uint32_t aB  = sa + SBH + ((lane & 7) + ((lane < 16) ? 0 : 8)) * SXSTR
                       + ((lane >> 3) & 1) * 16;
    const uint32_t aBl = aB + (uint32_t)(SBL - SBH);
    const uint32_t aP  = sa + SPH + ((lane & 7) + ((lane >> 3) & 1) * 8) * 80
                       + (lane >> 4) * 16;
    const uint32_t aVd = sa + SVH + ((lane & 7) + ((lane >> 3) & 1) * 8) * SXSTR
                       + w * 64 + ((lane < 16) ? 0 : 16);
    const uint32_t aVdl = aVd + (uint32_t)(SVL - SVH);

    const int r0 = rw + lr, r1 = rw + lr + 8;

#pragma unroll 1
    for (int t = 0; t < NT; t++) {
        CP_WAIT1();
        __syncthreads();

        float sf[4][4];
#pragma unroll
        for (int nt = 0; nt < 4; nt++)
#pragma unroll
            for (int i = 0; i < 4; i++) sf[nt][i] = 0.f;

        // ---- S: register double-buffered frags ----
        uint32_t fa[2][8], fb[2][16];
        ldsm4(&fa[0][0], aA);
        ldsm4(&fa[0][4], aAl);
        ldsm4(&fb[0][0], aB);
        ldsm4(&fb[0][4], aBl);
        ldsm4(&fb[0][8], aB + 16 * SXSTR);
        ldsm4(&fb[0][12], aBl + 16 * SXSTR);
#pragma unroll
        for (int kk = 0; kk < 16; kk++) {
            const int cur = kk & 1, nxt = cur ^ 1;
            if (kk < 15) {
                const uint32_t ko = (uint32_t)((kk + 1) * 32);
                ldsm4(&fa[nxt][0], aA  + ko);
                ldsm4(&fa[nxt][4], aAl + ko);
                ldsm4(&fb[nxt][0], aB  + ko);
                ldsm4(&fb[nxt][4], aBl + ko);
                ldsm4(&fb[nxt][8], aB  + 16 * SXSTR + ko);
                ldsm4(&fb[nxt][12], aBl + 16 * SXSTR + ko);
            }
            const uint32_t* ah = &fa[cur][0];
            const uint32_t* al = &fa[cur][4];
            const uint32_t* bh = &fb[cur][0];
            const uint32_t* bl = &fb[cur][4];
            const uint32_t* ch = &fb[cur][8];
            const uint32_t* cl = &fb[cur][12];
            mma16816(sf[0], ah, bh[0], bh[1]);
            mma16816(sf[0], ah, bl[0], bl[1]);
            mma16816(sf[0], al, bh[0], bh[1]);
            mma16816(sf[1], ah, bh[2], bh[3]);
            mma16816(sf[1], ah, bl[2], bl[3]);
            mma16816(sf[1], al, bh[2], bh[3]);
            mma16816(sf[2], ah, ch[0], ch[1]);
            mma16816(sf[2], ah, cl[0], cl[1]);
            mma16816(sf[2], al, ch[0], ch[1]);
            mma16816(sf[3], ah, ch[2], ch[3]);
            mma16816(sf[3], ah, cl[2], cl[3]);
            mma16816(sf[3], al, ch[2], ch[3]);
        }

        float mx0 = -1e30f, mx1 = -1e30f;
#pragma unroll
        for (int nt = 0; nt < 4; nt++) {
            int j = 8 * nt + 2 * tig;
            if (smk[j])     { sf[nt][0] = -1e30f; sf[nt][2] = -1e30f; }
            if (smk[j + 1]) { sf[nt][1] = -1e30f; sf[nt][3] = -1e30f; }
            mx0 = fmaxf(mx0, fmaxf(sf[nt][0], sf[nt][1]));
            mx1 = fmaxf(mx1, fmaxf(sf[nt][2], sf[nt][3]));
        }
        mx0 = fmaxf(mx0, __shfl_xor_sync(0xffffffffu, mx0, 1));
        mx0 = fmaxf(mx0, __shfl_xor_sync(0xffffffffu, mx0, 2));
        mx1 = fmaxf(mx1, __shfl_xor_sync(0xffffffffu, mx1, 1));
        mx1 = fmaxf(mx1, __shfl_xor_sync(0xffffffffu, mx1, 2));

        float mn0 = fmaxf(m0, mx0), mn1 = fmaxf(m1, mx1);
        float sc0 = exp2p((m0 - mn0) * L2E);
        float sc1 = exp2p((m1 - mn1) * L2E);
        m0 = mn0; m1 = mn1;

        uint32_t ph[8];
        float rs0 = 0.f, rs1 = 0.f;
#pragma unroll
        for (int nt = 0; nt < 4; nt++) {
            float p00 = exp2p((sf[nt][0] - mn0) * L2E);
            float p01 = exp2p((sf[nt][1] - mn0) * L2E);
            float p10 = exp2p((sf[nt][2] - mn1) * L2E);
            float p11 = exp2p((sf[nt][3] - mn1) * L2E);
            uint32_t h0 = cvt2bf(p00, p01);
            uint32_t h1 = cvt2bf(p10, p11);
            ph[nt * 2]     = h0;
            ph[nt * 2 + 1] = h1;
            rs0 += __uint_as_float(h0 << 16) + __uint_as_float(h0 & 0xffff0000u);
            rs1 += __uint_as_float(h1 << 16) + __uint_as_float(h1 & 0xffff0000u);
        }
        rs0 += __shfl_xor_sync(0xffffffffu, rs0, 1);
        rs0 += __shfl_xor_sync(0xffffffffu, rs0, 2);
        rs1 += __shfl_xor_sync(0xffffffffu, rs1, 1);
        rs1 += __shfl_xor_sync(0xffffffffu, rs1, 2);
        l0 = l0 * sc0 + rs0;
        l1 = l1 * sc1 + rs1;

#pragma unroll
        for (int nt = 0; nt < 4; nt++) {
            *(uint32_t*)(smc + SPH + r0 * 80 + 16 * nt + 4 * tig) = ph[nt * 2];
            *(uint32_t*)(smc + SPH + r1 * 80 + 16 * nt + 4 * tig) = ph[nt * 2 + 1];
        }
        if (tig == 0) { sSC[r0] = sc0; sSC[r1] = sc1; }
        __syncthreads();

        if (t < NT - 1) issueYp(t + 1);
        CP_COMMIT();

        if (t < NT - 1) { CP_WAIT1(); } else { CP_WAIT0(); }
        __syncthreads();

        // ---- PV: O[all rows, d32 slice] += Ph @ (Vh + Vl), P-frag prefetch.
        //      O-rescale folded in at k==0 (FFMA overlaps tensor). ----
#pragma unroll
        for (int k = 0; k < 2; k++) {
            uint32_t vh0[4], vl0[4], vh1[4], vl1[4];
            ldsm4t(vh0, aVd  + k * 16 * SXSTR);
            ldsm4t(vh1, aVd  + k * 16 * SXSTR + 32);
            ldsm4t(vl0, aVdl + k * 16 * SXSTR);
            ldsm4t(vl1, aVdl + k * 16 * SXSTR + 32);
            uint32_t pa[2][4];
            ldsm4(pa[0], aP + k * 32);
#pragma unroll
            for (int mg = 0; mg < 8; mg++) {
                const int cur = mg & 1, nxt = cur ^ 1;
                if (mg < 7) ldsm4(pa[nxt], aP + (mg + 1) * 1280 + k * 32);
                if (k == 0) {
                    float sA = sSC[mg * 16 + lr];
                    float sB = sSC[mg * 16 + lr + 8];
#pragma unroll
                    for (int df = 0; df < 4; df++) {
                        O[mg * 4 + df][0] *= sA; O[mg * 4 + df][1] *= sA;
                        O[mg * 4 + df][2] *= sB; O[mg * 4 + df][3] *= sB;
                    }
                }
                const uint32_t* pA = pa[cur];
                mma16816(O[mg * 4 + 0], pA, vh0[0], vh0[1]);
                mma16816(O[mg * 4 + 0], pA, vl0[0], vl0[1]);
                mma16816(O[mg * 4 + 1], pA, vh0[2], vh0[3]);
                mma16816(O[mg * 4 + 1], pA, vl0[2], vl0[3]);
                mma16816(O[mg * 4 + 2], pA, vh1[0], vh1[1]);
                mma16816(O[mg * 4 + 2], pA, vl1[0], vl1[1]);
                mma16816(O[mg * 4 + 3], pA, vh1[2], vh1[3]);
                mma16816(O[mg * 4 + 3], pA, vl1[2], vl1[3]);
            }
        }
        __syncthreads();

        if (t < NT - 1) issueYv(t + 1);
        CP_COMMIT();
    }

    if (tig == 0) { sSC[r0] = 1.0f / l0; sSC[r1] = 1.0f / l1; }
    __syncthreads();
#pragma unroll
    for (int mg = 0; mg < 8; mg++) {
        float iA = sSC[mg * 16 + lr];
        float iB = sSC[mg * 16 + lr + 8];
        float* oA = out + (size_t)(b * LXX + x0 + mg * 16 + lr) * DD + w * 32;
        float* oB = oA + 8 * DD;
#pragma unroll
        for (int df = 0; df < 4; df++) {
            int c = df * 8 + tig * 2;
            *(float2*)(oA + c) = make_float2(O[mg * 4 + df][0] * iA,
                                             O[mg * 4 + df][1] * iA);
            *(float2*)(oB + c) = make_float2(O[mg * 4 + df][2] * iB,
                                             O[mg * 4 + df][3] * iB);
        }
    }
}

// ---------------------------------------------------------------------------
extern "C" void kernel_launch(void* const* d_in, const int* in_sizes, int n_in,
                              void* d_out, int out_size)
{
    const float* x    = (const float*)d_in[0];
    const float* y    = (const float*)d_in[1];
    const int* mask   = (const int*)d_in[2];
    const float* W    = (const float*)d_in[3];
    const float* bias = (const float*)d_in[4];
    float* out        = (float*)d_out;

    split_W<<<(DD * DD) / (256 * 4), 256>>>(W);
    split_xy<<<(2 * BB * LXX * DD) / (256 * 4), 256>>>(x, y);

    cudaFuncSetAttribute(proj_mma_kernel,
                         cudaFuncAttributeMaxDynamicSharedMemorySize, PJ_TOT);
    proj_mma_kernel<<<dim3((BB * (LXX + LYY)) / 128, 2), 256, PJ_TOT>>>(bias);

    cudaFuncSetAttribute(attn_mma_kernel,
                         cudaFuncAttributeMaxDynamicSharedMemorySize, SMTOT);
    attn_mma_kernel<<<dim3(LXX / 128, BB), 256, SMTOT>>>(mask, out);
}

// round 14
// speedup vs baseline: 2.9310x; 1.0585x over previous
#include <cuda_runtime.h>
#include <cuda_bf16.h>
#include <cstdint>

#define BB 8
#define LXX 2048
#define LYY 2048
#define DD 256

// ---------------- global scratch (no cudaMalloc allowed) ----------------
__device__ __nv_bfloat16 g_x_h[BB * LXX * DD];    // raw x, bf16 hi/lo
__device__ __nv_bfloat16 g_x_l[BB * LXX * DD];
__device__ __nv_bfloat16 g_xp_h[BB * LXX * DD];
__device__ __nv_bfloat16 g_xp_l[BB * LXX * DD];
__device__ __nv_bfloat16 g_yp_h[BB * LYY * DD];
__device__ __nv_bfloat16 g_yp_l[BB * LYY * DD];
__device__ __nv_bfloat16 g_yv_h[BB * LYY * DD];   // raw y, bf16 hi/lo
__device__ __nv_bfloat16 g_yv_l[BB * LYY * DD];
__device__ __nv_bfloat16 g_W_h[DD * DD];
__device__ __nv_bfloat16 g_W_l[DD * DD];

// ---------------- helpers (portable PTX only: sm_80-era) ----------------
__device__ __forceinline__ uint32_t smem_u32(const void* p) {
    uint32_t a;
    asm("{ .reg .u64 t; cvta.to.shared.u64 t, %1; cvt.u32.u64 %0, t; }" : "=r"(a) : "l"(p));
    return a;
}
__device__ __forceinline__ void cpa16(uint32_t s, const void* g) {
    asm volatile("cp.async.cg.shared.global [%0], [%1], 16;" :: "r"(s), "l"(g));
}
__device__ __forceinline__ void cpa4(uint32_t s, const void* g) {
    asm volatile("cp.async.ca.shared.global [%0], [%1], 4;" :: "r"(s), "l"(g));
}
#define CP_COMMIT() asm volatile("cp.async.commit_group;" ::: "memory")
#define CP_WAIT0()  asm volatile("cp.async.wait_group 0;" ::: "memory")
#define CP_WAIT1()  asm volatile("cp.async.wait_group 1;" ::: "memory")

__device__ __forceinline__ void ldsm4(uint32_t r[4], uint32_t a) {
    asm volatile("ldmatrix.sync.aligned.m8n8.x4.shared.b16 {%0,%1,%2,%3}, [%4];"
                 : "=r"(r[0]), "=r"(r[1]), "=r"(r[2]), "=r"(r[3]) : "r"(a));
}
__device__ __forceinline__ void ldsm4t(uint32_t r[4], uint32_t a) {
    asm volatile("ldmatrix.sync.aligned.m8n8.x4.trans.shared.b16 {%0,%1,%2,%3}, [%4];"
                 : "=r"(r[0]), "=r"(r[1]), "=r"(r[2]), "=r"(r[3]) : "r"(a));
}
__device__ __forceinline__ void mma16816(float c[4], const uint32_t a[4],
                                         uint32_t b0, uint32_t b1) {
    asm volatile(
        "mma.sync.aligned.m16n8k16.row.col.f32.bf16.bf16.f32 "
        "{%0,%1,%2,%3}, {%4,%5,%6,%7}, {%8,%9}, {%0,%1,%2,%3};"
        : "+f"(c[0]), "+f"(c[1]), "+f"(c[2]), "+f"(c[3])
        : "r"(a[0]), "r"(a[1]), "r"(a[2]), "r"(a[3]), "r"(b0), "r"(b1));
}
__device__ __forceinline__ uint32_t cvt2bf(float lo, float hi) {
    uint32_t r;
    asm("cvt.rn.bf16x2.f32 %0, %1, %2;" : "=r"(r) : "f"(hi), "f"(lo));
    return r;
}
// MUFU exp2 (ex2.approx): ~2 ulp, returns 0 for very negative inputs.
__device__ __forceinline__ float ex2a(float x) {
    float r;
    asm("ex2.approx.f32 %0, %1;" : "=f"(r) : "f"(x));
    return r;
}
#define L2E 1.4426950408889634f

// ---------------------------------------------------------------------------
// Elementwise bf16 hi/lo splitters
// ---------------------------------------------------------------------------
__global__ __launch_bounds__(256)
void split_W(const float* __restrict__ W)
{
    size_t i = ((size_t)blockIdx.x * 256 + threadIdx.x) * 4;
    float4 v = *(const float4*)(W + i);
    float vv[4] = {v.x, v.y, v.z, v.w};
    __nv_bfloat16 h[4], l[4];
#pragma unroll
    for (int k = 0; k < 4; k++) {
        h[k] = __float2bfloat16_rn(vv[k]);
        l[k] = __float2bfloat16_rn(vv[k] - __bfloat162float(h[k]));
    }
    *(uint2*)&g_W_h[i] = *(uint2*)h;
    *(uint2*)&g_W_l[i] = *(uint2*)l;
}
// blocks [0, N/1024) -> x, rest -> y
__global__ __launch_bounds__(256)
void split_xy(const float* __restrict__ x, const float* __restrict__ y)
{
    const int half = (BB * LXX * DD) / (256 * 4);
    const float* src;
    __nv_bfloat16 *dh, *dl;
    size_t i;
    if (blockIdx.x < half) {
        src = x; dh = g_x_h; dl = g_x_l;
        i = ((size_t)blockIdx.x * 256 + threadIdx.x) * 4;
    } else {
        src = y; dh = g_yv_h; dl = g_yv_l;
        i = ((size_t)(blockIdx.x - half) * 256 + threadIdx.x) * 4;
    }
    float4 v = *(const float4*)(src + i);
    float vv[4] = {v.x, v.y, v.z, v.w};
    __nv_bfloat16 h[4], l[4];
#pragma unroll
    for (int k = 0; k < 4; k++) {
        h[k] = __float2bfloat16_rn(vv[k]);
        l[k] = __float2bfloat16_rn(vv[k] - __bfloat162float(h[k]));
    }
    *(uint2*)&dh[i] = *(uint2*)h;
    *(uint2*)&dl[i] = *(uint2*)l;
}

// ---------------------------------------------------------------------------
// Tensor-core projection v2 (unchanged from R13): C = relu(A @ W^T + b).
// CTA = 128x128; A and W both streamed per k32 chunk, double-buffered;
// smem 80KB => 2 CTAs/SM. 3-pass hh+hl+lh; W frags register double-buffered.
// ---------------------------------------------------------------------------
#define PJ_AH 0
#define PJ_AL 10240
#define PJ_WH 20480
#define PJ_WL 30720
#define PJ_STG 40960
#define PJ_TOT (2 * PJ_STG)

__global__ __launch_bounds__(256, 2)
void proj_mma_kernel(const float* __restrict__ bias)
{
    extern __shared__ char smc[];
    const uint32_t sa = smem_u32(smc);
    const int tid  = threadIdx.x;
    const int w    = tid >> 5;
    const int lane = tid & 31;
    const int lr   = lane >> 2;
    const int tig  = lane & 3;
    const int rw   = w * 16;
    const int wcol0 = blockIdx.y * 128;
    const int row0  = blockIdx.x * 128;
    const bool isx  = row0 < BB * LXX;
    const int arow0 = isx ? row0 : row0 - BB * LXX;

    const __nv_bfloat16* __restrict__ Ah = isx ? g_x_h : g_yv_h;
    const __nv_bfloat16* __restrict__ Al = isx ? g_x_l : g_yv_l;
    __nv_bfloat16* __restrict__ Ch = isx ? g_xp_h : g_yp_h;
    __nv_bfloat16* __restrict__ Cl = isx ? g_xp_l : g_yp_l;

    const int pre_r = tid >> 1, pre_hb = tid & 1;

    auto pref = [&](int s, int kc) {
        const uint32_t st = sa + (uint32_t)(s * PJ_STG + pre_r * 80 + pre_hb * 32);
        const size_t ao = (size_t)(arow0 + pre_r) * DD + kc * 32 + pre_hb * 16;
        const size_t wo = (size_t)(wcol0 + pre_r) * DD + kc * 32 + pre_hb * 16;
        cpa16(st + PJ_AH,      Ah + ao);  cpa16(st + PJ_AH + 16,  Ah + ao + 8);
        cpa16(st + PJ_AL,      Al + ao);  cpa16(st + PJ_AL + 16,  Al + ao + 8);
        cpa16(st + PJ_WH,      g_W_h + wo); cpa16(st + PJ_WH + 16, g_W_h + wo + 8);
        cpa16(st + PJ_WL,      g_W_l + wo); cpa16(st + PJ_WL + 16, g_W_l + wo + 8);
    };
    pref(0, 0);
    CP_COMMIT();

    float O[16][4];
#pragma unroll
    for (int i = 0; i < 16; i++) { O[i][0] = O[i][1] = O[i][2] = O[i][3] = 0.f; }

    const uint32_t aAo = (uint32_t)(PJ_AH + (rw + (lane & 7) + ((lane >> 3) & 1) * 8) * 80
                        + (lane >> 4) * 16);
    const uint32_t aWo = (uint32_t)(PJ_WH + ((lane & 7) + ((lane < 16) ? 0 : 8)) * 80
                        + ((lane >> 3) & 1) * 16);

#pragma unroll 1
    for (int kc = 0; kc < 8; kc++) {
        const int s = kc & 1;
        if (kc < 7) { pref(s ^ 1, kc + 1); CP_COMMIT(); CP_WAIT1(); }
        else        { CP_WAIT0(); }
        __syncthreads();

        const uint32_t stb = sa + (uint32_t)(s * PJ_STG);
        const uint32_t aA  = stb + aAo;
        const uint32_t aAl = aA + (PJ_AL - PJ_AH);
        const uint32_t aW  = stb + aWo;
        const uint32_t aWl = aW + (PJ_WL - PJ_WH);
#pragma unroll
        for (int kk = 0; kk < 2; kk++) {
            uint32_t ah[4], al[4];
            ldsm4(ah, aA  + kk * 32);
            ldsm4(al, aAl + kk * 32);
            uint32_t wb[2][8];
            ldsm4(&wb[0][0], aW  + kk * 32);
            ldsm4(&wb[0][4], aWl + kk * 32);
#pragma unroll
            for (int g = 0; g < 8; g++) {
                const int cur = g & 1, nxt = cur ^ 1;
                if (g < 7) {
                    ldsm4(&wb[nxt][0], aW  + (g + 1) * 1280 + kk * 32);
                    ldsm4(&wb[nxt][4], aWl + (g + 1) * 1280 + kk * 32);
                }
                const uint32_t* bh = &wb[cur][0];
                const uint32_t* bl = &wb[cur][4];
                mma16816(O[2 * g],     ah, bh[0], bh[1]);
                mma16816(O[2 * g],     ah, bl[0], bl[1]);
                mma16816(O[2 * g],     al, bh[0], bh[1]);
                mma16816(O[2 * g + 1], ah, bh[2], bh[3]);
                mma16816(O[2 * g + 1], ah, bl[2], bl[3]);
                mma16816(O[2 * g + 1], al, bh[2], bh[3]);
            }
        }
        __syncthreads();
    }

    // ---- epilogue: bias + relu + h/l split + store ----
    const int r0g = arow0 + rw + lr;
#pragma unroll
    for (int f = 0; f < 16; f++) {
        int c = wcol0 + f * 8 + tig * 2;
        float b0 = __ldg(bias + c), b1 = __ldg(bias + c + 1);
        {
            float v0 = fmaxf(O[f][0] + b0, 0.f), v1 = fmaxf(O[f][1] + b1, 0.f);
            uint32_t h = cvt2bf(v0, v1);
            float q0 = v0 - __uint_as_float(h << 16);
            float q1 = v1 - __uint_as_float(h & 0xffff0000u);
            uint32_t l = cvt2bf(q0, q1);
            size_t o = (size_t)r0g * DD + c;
            *(uint32_t*)&Ch[o] = h;
            *(uint32_t*)&Cl[o] = l;
        }
        {
            float v0 = fmaxf(O[f][2] + b0, 0.f), v1 = fmaxf(O[f][3] + b1, 0.f);
            uint32_t h = cvt2bf(v0, v1);
            float q0 = v0 - __uint_as_float(h << 16);
            float q1 = v1 - __uint_as_float(h & 0xffff0000u);
            uint32_t l = cvt2bf(q0, q1);
            size_t o = (size_t)(r0g + 8) * DD + c;
            *(uint32_t*)&Ch[o] = h;
            *(uint32_t*)&Cl[o] = l;
        }
    }
}

// ---------------------------------------------------------------------------
// Fused mma.sync attention: 256 threads, XTILE 128, JTILE 32.
// S phase: 3-pass hh+hl+lh, register double-buffered frags.
// Softmax: MUFU ex2.approx (was FFMA polynomial).
// PV: d-split + P-frag prefetch; O-rescale folded in at k==0.
// Per tile: one barrier+wait fewer than R13 (single mid-tile barrier covers
// P visibility + yV visibility + S-reads-done).
// ---------------------------------------------------------------------------
#define SXSTR 528
#define SXH 0
#define SXL (SXH + 128 * SXSTR)
#define SBH (SXL + 128 * SXSTR)
#define SBL (SBH + 32 * SXSTR)
#define SVH (SBL + 32 * SXSTR)
#define SVL (SVH + 32 * SXSTR)
#define SPH (SVL + 32 * SXSTR)
#define SSC (SPH + 128 * 80)
#define SMK (SSC + 512)
#define SMTOT (SMK + 128)
#define NT (LYY / 32)

__global__ __launch_bounds__(256, 1)
void attn_mma_kernel(const int* __restrict__ mask, float* __restrict__ out)
{
    extern __shared__ char smc[];
    const uint32_t sa = smem_u32(smc);
    const int tid  = threadIdx.x;
    const int w    = tid >> 5;
    const int lane = tid & 31;
    const int lr   = lane >> 2;
    const int tig  = lane & 3;
    const int b    = blockIdx.y;
    const int x0   = blockIdx.x * 128;
    const int rw   = w * 16;

    const int* mB = mask + (size_t)b * LYY;
    const size_t gyB = (size_t)(b * LYY) * DD;
    const int pr = tid >> 3, pcb = tid & 7;

    auto issueYp = [&](int t) {
        size_t gro = gyB + (size_t)(t * 32 + pr) * DD;
        uint32_t o = sa + (uint32_t)(pr * SXSTR);
#pragma unroll
        for (int i = 0; i < 4; i++) {
            int c = pcb + 8 * i;
            cpa16(o + SBH + c * 16, g_yp_h + gro + c * 8);
            cpa16(o + SBL + c * 16, g_yp_l + gro + c * 8);
        }
        if (tid < 32) cpa4(sa + SMK + tid * 4, mB + t * 32 + tid);
    };
    auto issueYv = [&](int t) {
        size_t gro = gyB + (size_t)(t * 32 + pr) * DD;
        uint32_t o = sa + (uint32_t)(pr * SXSTR);
#pragma unroll
        for (int i = 0; i < 4; i++) {
            int c = pcb + 8 * i;
            cpa16(o + SVH + c * 16, g_yv_h + gro + c * 8);
            cpa16(o + SVL + c * 16, g_yv_l + gro + c * 8);
        }
    };

    {
        int r = tid >> 1;
        const __nv_bfloat16* srch = g_xp_h + (size_t)(b * LXX + x0 + r) * DD;
        const __nv_bfloat16* srcl = g_xp_l + (size_t)(b * LXX + x0 + r) * DD;
        uint32_t dh = sa + SXH + r * SXSTR;
        uint32_t dl = sa + SXL + r * SXSTR;
#pragma unroll
        for (int i = 0; i < 16; i++) {
            int c = (tid & 1) + 2 * i;
            cpa16(dh + c * 16, srch + c * 8);
            cpa16(dl + c * 16, srcl + c * 8);
        }
    }
    CP_COMMIT();
    issueYp(0);
    CP_COMMIT();
    issueYv(0);
    CP_COMMIT();

    const int* smk = (const int*)(smc + SMK);
    float* sSC = (float*)(smc + SSC);

    float O[32][4];
#pragma unroll
    for (int i = 0; i < 32; i++) { O[i][0] = O[i][1] = O[i][2] = O[i][3] = 0.f; }
    float m0 = -1e30f, m1 = -1e30f, l0 = 0.f, l1 = 0.f;

    const uint32_t aA  = sa + SXH + (rw + (lane & 7) + ((lane >> 3) & 1) * 8) * SXSTR
                       + (lane >> 4) * 16;
    const uint32_t aAl = aA + (uint32_t)(SXL - SXH);
    const uint32_t aB  = sa + SBH + ((lane & 7) + ((lane < 16) ? 0 : 8)) * SXSTR
                       + ((lane >> 3) & 1) * 16;
    const uint32_t aBl = aB + (uint32_t)(SBL - SBH);
    const uint32_t aP  = sa + SPH + ((lane & 7) + ((lane >> 3) & 1) * 8) * 80
                       + (lane >> 4) * 16;
    const uint32_t aVd = sa + SVH + ((lane & 7) + ((lane >> 3) & 1) * 8) * SXSTR
                       + w * 64 + ((lane < 16) ? 0 : 16);
    const uint32_t aVdl = aVd + (uint32_t)(SVL - SVH);

    const int r0 = rw + lr, r1 = rw + lr + 8;

#pragma unroll 1
    for (int t = 0; t < NT; t++) {
        CP_WAIT1();                    // Yp(t) (+X at t=0) arrived
        __syncthreads();

        float sf[4][4];
#pragma unroll
        for (int nt = 0; nt < 4; nt++)
#pragma unroll
            for (int i = 0; i < 4; i++) sf[nt][i] = 0.f;

        // ---- S: register double-buffered frags ----
        uint32_t fa[2][8], fb[2][16];
        ldsm4(&fa[0][0], aA);
        ldsm4(&fa[0][4], aAl);
        ldsm4(&fb[0][0], aB);
        ldsm4(&fb[0][4], aBl);
        ldsm4(&fb[0][8], aB + 16 * SXSTR);
        ldsm4(&fb[0][12], aBl + 16 * SXSTR);
#pragma unroll
        for (int kk = 0; kk < 16; kk++) {
            const int cur = kk & 1, nxt = cur ^ 1;
            if (kk < 15) {
                const uint32_t ko = (uint32_t)((kk + 1) * 32);
                ldsm4(&fa[nxt][0], aA  + ko);
                ldsm4(&fa[nxt][4], aAl + ko);
                ldsm4(&fb[nxt][0], aB  + ko);
                ldsm4(&fb[nxt][4], aBl + ko);
                ldsm4(&fb[nxt][8], aB  + 16 * SXSTR + ko);
                ldsm4(&fb[nxt][12], aBl + 16 * SXSTR + ko);
            }
            const uint32_t* ah = &fa[cur][0];
            const uint32_t* al = &fa[cur][4];
            const uint32_t* bh = &fb[cur][0];
            const uint32_t* bl = &fb[cur][4];
            const uint32_t* ch = &fb[cur][8];
            const uint32_t* cl = &fb[cur][12];
            mma16816(sf[0], ah, bh[0], bh[1]);
            mma16816(sf[0], ah, bl[0], bl[1]);
            mma16816(sf[0], al, bh[0], bh[1]);
            mma16816(sf[1], ah, bh[2], bh[3]);
            mma16816(sf[1], ah, bl[2], bl[3]);
            mma16816(sf[1], al, bh[2], bh[3]);
            mma16816(sf[2], ah, ch[0], ch[1]);
            mma16816(sf[2], ah, cl[0], cl[1]);
            mma16816(sf[2], al, ch[0], ch[1]);
            mma16816(sf[3], ah, ch[2], ch[3]);
            mma16816(sf[3], ah, cl[2], cl[3]);
            mma16816(sf[3], al, ch[2], ch[3]);
        }

        // ---- mask + online softmax (MUFU exp) ----
        float mx0 = -1e30f, mx1 = -1e30f;
#pragma unroll
        for (int nt = 0; nt < 4; nt++) {
            int j = 8 * nt + 2 * tig;
            if (smk[j])     { sf[nt][0] = -1e30f; sf[nt][2] = -1e30f; }
            if (smk[j + 1]) { sf[nt][1] = -1e30f; sf[nt][3] = -1e30f; }
            mx0 = fmaxf(mx0, fmaxf(sf[nt][0], sf[nt][1]));
            mx1 = fmaxf(mx1, fmaxf(sf[nt][2], sf[nt][3]));
        }
        mx0 = fmaxf(mx0, __shfl_xor_sync(0xffffffffu, mx0, 1));
        mx0 = fmaxf(mx0, __shfl_xor_sync(0xffffffffu, mx0, 2));
        mx1 = fmaxf(mx1, __shfl_xor_sync(0xffffffffu, mx1, 1));
        mx1 = fmaxf(mx1, __shfl_xor_sync(0xffffffffu, mx1, 2));

        float mn0 = fmaxf(m0, mx0), mn1 = fmaxf(m1, mx1);
        float sc0 = ex2a((m0 - mn0) * L2E);
        float sc1 = ex2a((m1 - mn1) * L2E);
        m0 = mn0; m1 = mn1;
        const float mnL0 = mn0 * L2E, mnL1 = mn1 * L2E;

        uint32_t ph[8];
        float rs0 = 0.f, rs1 = 0.f;
#pragma unroll
        for (int nt = 0; nt < 4; nt++) {
            float p00 = ex2a(fmaf(sf[nt][0], L2E, -mnL0));
            float p01 = ex2a(fmaf(sf[nt][1], L2E, -mnL0));
            float p10 = ex2a(fmaf(sf[nt][2], L2E, -mnL1));
            float p11 = ex2a(fmaf(sf[nt][3], L2E, -mnL1));
            uint32_t h0 = cvt2bf(p00, p01);
            uint32_t h1 = cvt2bf(p10, p11);
            ph[nt * 2]     = h0;
            ph[nt * 2 + 1] = h1;
            rs0 += __uint_as_float(h0 << 16) + __uint_as_float(h0 & 0xffff0000u);
            rs1 += __uint_as_float(h1 << 16) + __uint_as_float(h1 & 0xffff0000u);
        }
        rs0 += __shfl_xor_sync(0xffffffffu, rs0, 1);
        rs0 += __shfl_xor_sync(0xffffffffu, rs0, 2);
        rs1 += __shfl_xor_sync(0xffffffffu, rs1, 1);
        rs1 += __shfl_xor_sync(0xffffffffu, rs1, 2);
        l0 = l0 * sc0 + rs0;
        l1 = l1 * sc1 + rs1;

        // write P-hi + per-row scale
#pragma unroll
        for (int nt = 0; nt < 4; nt++) {
            *(uint32_t*)(smc + SPH + r0 * 80 + 16 * nt + 4 * tig) = ph[nt * 2];
            *(uint32_t*)(smc + SPH + r1 * 80 + 16 * nt + 4 * tig) = ph[nt * 2 + 1];
        }
        if (tig == 0) { sSC[r0] = sc0; sSC[r1] = sc1; }

        // single mid-tile barrier: P visible, yV(t) visible, all S reads done
        CP_WAIT0();
        __syncthreads();

        if (t < NT - 1) issueYp(t + 1);
        CP_COMMIT();

        // ---- PV: O += Ph @ (Vh + Vl); rescale folded in at k==0 ----
#pragma unroll
        for (int k = 0; k < 2; k++) {
            uint32_t vh0[4], vl0[4], vh1[4], vl1[4];
            ldsm4t(vh0, aVd  + k * 16 * SXSTR);
            ldsm4t(vh1, aVd  + k * 16 * SXSTR + 32);
            ldsm4t(vl0, aVdl + k * 16 * SXSTR);
            ldsm4t(vl1, aVdl + k * 16 * SXSTR + 32);
            uint32_t pa[2][4];
            ldsm4(pa[0], aP + k * 32);
#pragma unroll
            for (int mg = 0; mg < 8; mg++) {
                const int cur = mg & 1, nxt = cur ^ 1;
                if (mg < 7) ldsm4(pa[nxt], aP + (mg + 1) * 1280 + k * 32);
                if (k == 0) {
                    float sA = sSC[mg * 16 + lr];
                    float sB = sSC[mg * 16 + lr + 8];
#pragma unroll
                    for (int df = 0; df < 4; df++) {
                        O[mg * 4 + df][0] *= sA; O[mg * 4 + df][1] *= sA;
                        O[mg * 4 + df][2] *= sB; O[mg * 4 + df][3] *= sB;
                    }
                }
                const uint32_t* pA = pa[cur];
                mma16816(O[mg * 4 + 0], pA, vh0[0], vh0[1]);
                mma16816(O[mg * 4 + 0], pA, vl0[0], vl0[1]);
                mma16816(O[mg * 4 + 1], pA, vh0[2], vh0[3]);
                mma16816(O[mg * 4 + 1], pA, vl0[2], vl0[3]);
                mma16816(O[mg * 4 + 2], pA, vh1[0], vh1[1]);
                mma16816(O[mg * 4 + 2], pA, vl1[0], vl1[1]);
                mma16816(O[mg * 4 + 3], pA, vh1[2], vh1[3]);
                mma16816(O[mg * 4 + 3], pA, vl1[2], vl1[3]);
            }
        }
        __syncthreads();               // V + P reads done before overwrite

        if (t < NT - 1) issueYv(t + 1);
        CP_COMMIT();
    }

    if (tig == 0) { sSC[r0] = 1.0f / l0; sSC[r1] = 1.0f / l1; }
    __syncthreads();
#pragma unroll
    for (int mg = 0; mg < 8; mg++) {
        float iA = sSC[mg * 16 + lr];
        float iB = sSC[mg * 16 + lr + 8];
        float* oA = out + (size_t)(b * LXX + x0 + mg * 16 + lr) * DD + w * 32;
        float* oB = oA + 8 * DD;
#pragma unroll
        for (int df = 0; df < 4; df++) {
            int c = df * 8 + tig * 2;
            *(float2*)(oA + c) = make_float2(O[mg * 4 + df][0] * iA,
                                             O[mg * 4 + df][1] * iA);
            *(float2*)(oB + c) = make_float2(O[mg * 4 + df][2] * iB,
                                             O[mg * 4 + df][3] * iB);
        }
    }
}

// ---------------------------------------------------------------------------
extern "C" void kernel_launch(void* const* d_in, const int* in_sizes, int n_in,
                              void* d_out, int out_size)
{
    const float* x    = (const float*)d_in[0];
    const float* y    = (const float*)d_in[1];
    const int* mask   = (const int*)d_in[2];
    const float* W    = (const float*)d_in[3];
    const float* bias = (const float*)d_in[4];
    float* out        = (float*)d_out;

    split_W<<<(DD * DD) / (256 * 4), 256>>>(W);
    split_xy<<<(2 * BB * LXX * DD) / (256 * 4), 256>>>(x, y);

    cudaFuncSetAttribute(proj_mma_kernel,
                         cudaFuncAttributeMaxDynamicSharedMemorySize, PJ_TOT);
    proj_mma_kernel<<<dim3((BB * (LXX + LYY)) / 128, 2), 256, PJ_TOT>>>(bias);

    cudaFuncSetAttribute(attn_mma_kernel,
                         cudaFuncAttributeMaxDynamicSharedMemorySize, SMTOT);
    attn_mma_kernel<<<dim3(LXX / 128, BB), 256, SMTOT>>>(mask, out);
}